// round 9
// baseline (speedup 1.0000x reference)
#include <cuda_runtime.h>
#include <cuda_fp16.h>
#include <cstdint>

#define NB 4096   // tokens
#define NH 1024   // hidden
#define ND 4096   // expert dim
#define NE 8      // experts
#define NSPL 2    // split-K for GEMM2 (partials via STG, no atomics)

// ---------------- scratch (__device__ globals: allocation-guard safe) ----------------
__device__ __half g_xh [(size_t)NB * NH];              //   8 MB
__device__ __half g_w1h[(size_t)NE * NH * ND];         //  64 MB
__device__ __half g_w2h[(size_t)NE * ND * NH];         //  64 MB
__device__ __half g_h  [(size_t)NE * NB * ND];         // 256 MB
__device__ float  g_part[(size_t)NSPL * NE * NB * NH]; // 256 MB split partials
__device__ int    g_cnt[NE];
__device__ int    g_idx[NE * NB];
__device__ float  g_scale[NE * NB];
__device__ int    g_loc[NB * 2];
__device__ float  g_psum[NE];
__device__ float  g_rsum[NE];

// ---------------- helpers ----------------
__device__ __forceinline__ uint32_t smem_u32(const void* p) {
    return (uint32_t)__cvta_generic_to_shared(p);
}
__device__ __forceinline__ void cp16(uint32_t smem, const void* gmem) {
    asm volatile("cp.async.cg.shared.global [%0], [%1], 16;\n"
                 :: "r"(smem), "l"(gmem) : "memory");
}

// ---------------- prep 1: w1 fp32->fp16 + zero routing state (launch #1) ----------------
__global__ void prep_w1_kernel(const float* __restrict__ w1) {
    size_t i = (size_t)blockIdx.x * blockDim.x + threadIdx.x;
    if (i < (size_t)NE * NH * ND / 4) {
        float4 v = reinterpret_cast<const float4*>(w1)[i];
        __half2* d2 = reinterpret_cast<__half2*>(g_w1h) + i * 2;
        d2[0] = __floats2half2_rn(v.x, v.y);
        d2[1] = __floats2half2_rn(v.z, v.w);
    }
    if (i < NE) { g_cnt[i] = 0; g_psum[i] = 0.f; g_rsum[i] = 0.f; }
}

// ---------------- prep 2: w2 + x fp32->fp16 (launch #2) ----------------
__global__ void prep_w2_kernel(const float* __restrict__ w2,
                               const float* __restrict__ x) {
    size_t i = (size_t)blockIdx.x * blockDim.x + threadIdx.x;
    if (i < (size_t)NE * ND * NH / 4) {
        float4 v = reinterpret_cast<const float4*>(w2)[i];
        __half2* d2 = reinterpret_cast<__half2*>(g_w2h) + i * 2;
        d2[0] = __floats2half2_rn(v.x, v.y);
        d2[1] = __floats2half2_rn(v.z, v.w);
    }
    if (i < (size_t)NB * NH / 4) {
        float4 v = reinterpret_cast<const float4*>(x)[i];
        __half2* d2 = reinterpret_cast<__half2*>(g_xh) + i * 2;
        d2[0] = __floats2half2_rn(v.x, v.y);
        d2[1] = __floats2half2_rn(v.z, v.w);
    }
}

// ---------------- gating (launch #3) ----------------
__global__ void gate_kernel(const float* __restrict__ x,
                            const float* __restrict__ gw,
                            const float* __restrict__ gb) {
    __shared__ float sx[NH];
    __shared__ float slog[NE];
    const int b = blockIdx.x, tid = threadIdx.x;
    for (int i = tid; i < NH; i += 256) sx[i] = x[(size_t)b * NH + i];
    __syncthreads();
    const int w = tid >> 5, lane = tid & 31;
    float s = 0.f;
    for (int i = lane; i < NH; i += 32) s += sx[i] * gw[i * NE + w];
    #pragma unroll
    for (int o = 16; o; o >>= 1) s += __shfl_xor_sync(0xffffffffu, s, o);
    if (lane == 0) slog[w] = s + gb[w];
    __syncthreads();
    if (tid == 0) {
        float p[NE];
        float mx = slog[0];
        #pragma unroll
        for (int e = 1; e < NE; e++) mx = fmaxf(mx, slog[e]);
        float den = 0.f;
        #pragma unroll
        for (int e = 0; e < NE; e++) { p[e] = expf(slog[e] - mx); den += p[e]; }
        float inv = 1.f / den;
        #pragma unroll
        for (int e = 0; e < NE; e++) p[e] *= inv;
        int e1 = 0; float p1 = p[0];
        #pragma unroll
        for (int e = 1; e < NE; e++) if (p[e] > p1) { p1 = p[e]; e1 = e; }
        int e2 = (e1 == 0) ? 1 : 0; float p2 = p[e2];
        #pragma unroll
        for (int e = 0; e < NE; e++)
            if (e != e1 && p[e] > p2) { p2 = p[e]; e2 = e; }
        int pos = atomicAdd(&g_cnt[e1], 1);
        g_idx[e1 * NB + pos] = b; g_scale[e1 * NB + pos] = p1 * 0.5f;
        g_loc[b * 2 + 0] = e1 * NB + pos;
        pos = atomicAdd(&g_cnt[e2], 1);
        g_idx[e2 * NB + pos] = b; g_scale[e2 * NB + pos] = p2 * 0.5f;
        g_loc[b * 2 + 1] = e2 * NB + pos;
        #pragma unroll
        for (int e = 0; e < NE; e++) atomicAdd(&g_psum[e], p[e]);
        atomicAdd(&g_rsum[e1], 1.f);
        atomicAdd(&g_rsum[e2], 1.f);
    }
}

// ---------------- grouped GEMM: CTA 128x128, 256 thr, warp 32x64, K-chunk 32, 4-stage ring ----------------
// smem/stage: A 128 x 80B = 10240, B 32 x 272B = 8704; 4 stages = 75776
// prefetch distance 3 (wait_group 2 steady state) -> ~900cyc coverage > 577cyc DRAM latency
// ISB==false: h = relu(Xg @ W1 + b1)
// ISB==true : g_part[split][e-slot] = Xh @ W2 chunk   (plain STG; combine reduces)
template<int KLEN, int NDIM, bool ISB, int NSPLIT>
__global__ void __launch_bounds__(256, 2)
moe_gemm(const float* __restrict__ bias) {
    constexpr int KT   = KLEN / 32;
    constexpr int ASTG = 10240, BSTG = 8704;
    const int zi    = blockIdx.z;
    const int e     = (NSPLIT == 1) ? zi : (zi >> 1);
    const int split = (NSPLIT == 1) ? 0  : (zi & 1);
    const int cnt = g_cnt[e];
    const int m0  = blockIdx.y * 128;
    if (m0 >= cnt) return;
    const int n0    = blockIdx.x * 128;
    const int kbase = split * KLEN;
    const int tid   = threadIdx.x;

    extern __shared__ __align__(1024) char smem[];
    const uint32_t sA = smem_u32(smem);          // 4 * 10240
    const uint32_t sB = sA + 4 * ASTG;           // 4 * 8704

    // ---- gmem source pointers ----
    const int ar = tid >> 1;                      // A row (0..127), 2 threads/row
    const __half* Arow;
    if (ISB) {
        Arow = g_h + ((size_t)e * NB + m0 + ar) * ND + kbase;
    } else {
        const int s0  = m0 + ar;
        const int tok = g_idx[e * NB + (s0 < cnt ? s0 : 0)];
        Arow = g_xh + (size_t)tok * NH;
    }
    const __half* W = (ISB ? g_w2h : g_w1h)
                    + (size_t)e * (size_t)(KLEN * NSPLIT) * NDIM
                    + (size_t)kbase * NDIM + n0;
    const int br = tid >> 3;                      // B row (0..31), 8 threads/row

    auto load_stage = [&](int chunk, int s) {
        const uint32_t as = sA + s * ASTG + ar * 80;
        const __half* ag = Arow + chunk * 32;
        #pragma unroll
        for (int j = 0; j < 2; j++) {
            const int c4 = (tid & 1) * 2 + j;     // 16B col 0..3
            cp16(as + c4 * 16, ag + c4 * 8);
        }
        const uint32_t bs = sB + s * BSTG + br * 272;
        const __half* bg = W + (size_t)(chunk * 32 + br) * NDIM;
        #pragma unroll
        for (int j = 0; j < 2; j++) {
            const int cc = (tid & 7) * 2 + j;     // 16B col 0..15
            cp16(bs + cc * 16, bg + cc * 8);
        }
        asm volatile("cp.async.commit_group;" ::: "memory");
    };

    float acc[2][8][4];
    #pragma unroll
    for (int i = 0; i < 2; i++)
        #pragma unroll
        for (int j = 0; j < 8; j++)
            #pragma unroll
            for (int q = 0; q < 4; q++) acc[i][j][q] = 0.f;

    const int lane = tid & 31, warp = tid >> 5;
    const int wm = (warp & 3) * 32, wn = (warp >> 2) * 64;
    const uint32_t aoff = (uint32_t)(wm + (lane & 15)) * 80 + (lane >> 4) * 16;
    const uint32_t boff = (uint32_t)(lane & 15) * 272 + (uint32_t)(wn + (lane >> 4) * 8) * 2;

    load_stage(0, 0);
    load_stage(1, 1);
    load_stage(2, 2);

    for (int i = 0; i < KT; i++) {
        if (i < KT - 2)       asm volatile("cp.async.wait_group 2;" ::: "memory");
        else if (i == KT - 2) asm volatile("cp.async.wait_group 1;" ::: "memory");
        else                  asm volatile("cp.async.wait_group 0;" ::: "memory");
        __syncthreads();
        if (i + 3 < KT) load_stage(i + 3, (i + 3) & 3);

        const int s = i & 3;
        const uint32_t ab = sA + s * ASTG + aoff;
        const uint32_t bb = sB + s * BSTG + boff;
        #pragma unroll
        for (int ks = 0; ks < 2; ks++) {
            uint32_t a[2][4], b[4][4];
            #pragma unroll
            for (int im = 0; im < 2; im++) {
                asm volatile("ldmatrix.sync.aligned.m8n8.x4.shared.b16 {%0,%1,%2,%3}, [%4];"
                             : "=r"(a[im][0]), "=r"(a[im][1]), "=r"(a[im][2]), "=r"(a[im][3])
                             : "r"(ab + im * 16 * 80 + ks * 32));
            }
            #pragma unroll
            for (int g = 0; g < 4; g++) {
                asm volatile("ldmatrix.sync.aligned.m8n8.x4.trans.shared.b16 {%0,%1,%2,%3}, [%4];"
                             : "=r"(b[g][0]), "=r"(b[g][1]), "=r"(b[g][2]), "=r"(b[g][3])
                             : "r"(bb + ks * 16 * 272 + g * 32));
            }
            #pragma unroll
            for (int im = 0; im < 2; im++)
                #pragma unroll
                for (int jn = 0; jn < 8; jn++) {
                    const uint32_t b0 = b[jn >> 1][(jn & 1) * 2 + 0];
                    const uint32_t b1 = b[jn >> 1][(jn & 1) * 2 + 1];
                    asm volatile("mma.sync.aligned.m16n8k16.row.col.f32.f16.f16.f32 "
                                 "{%0,%1,%2,%3},{%4,%5,%6,%7},{%8,%9},{%0,%1,%2,%3};"
                                 : "+f"(acc[im][jn][0]), "+f"(acc[im][jn][1]),
                                   "+f"(acc[im][jn][2]), "+f"(acc[im][jn][3])
                                 : "r"(a[im][0]), "r"(a[im][1]), "r"(a[im][2]), "r"(a[im][3]),
                                   "r"(b0), "r"(b1));
                }
        }
    }

    // ---- epilogue ----
    const int rb = lane >> 2;
    const int cb = (lane & 3) * 2;
    #pragma unroll
    for (int im = 0; im < 2; im++) {
        #pragma unroll
        for (int h = 0; h < 2; h++) {
            const int row  = wm + im * 16 + rb + h * 8;
            const int slot = m0 + row;
            if (slot >= cnt) continue;
            if (!ISB) {
                __half* drow = &g_h[((size_t)e * NB + slot) * ND + n0 + wn];
                #pragma unroll
                for (int jn = 0; jn < 8; jn++) {
                    const int gc = n0 + wn + jn * 8 + cb;
                    float v0 = fmaxf(acc[im][jn][h * 2 + 0] + bias[e * NDIM + gc],     0.f);
                    float v1 = fmaxf(acc[im][jn][h * 2 + 1] + bias[e * NDIM + gc + 1], 0.f);
                    *reinterpret_cast<__half2*>(drow + jn * 8 + cb) = __floats2half2_rn(v0, v1);
                }
            } else {
                float* prow = g_part + ((size_t)split * (NE * NB) + (size_t)e * NB + slot) * NH
                            + n0 + wn;
                #pragma unroll
                for (int jn = 0; jn < 8; jn++) {
                    float2 v = make_float2(acc[im][jn][h * 2 + 0], acc[im][jn][h * 2 + 1]);
                    *reinterpret_cast<float2*>(prow + jn * 8 + cb) = v;
                }
            }
        }
    }
}

// ---------------- combine: y[b] = sum_j sc_j * (sum_s P[s][loc_j] + b2[e_j]) ----------------
__global__ void __launch_bounds__(256)
combine_kernel(const float* __restrict__ b2, float* __restrict__ y) {
    const int b   = blockIdx.x;
    const int tid = threadIdx.x;                  // 256 threads x float4 -> 1024 cols
    const int l1 = g_loc[b * 2 + 0];
    const int l2 = g_loc[b * 2 + 1];
    const int e1 = l1 >> 12, e2 = l2 >> 12;       // NB = 4096 = 2^12
    const float s1 = g_scale[l1], s2 = g_scale[l2];

    const float4* P = reinterpret_cast<const float4*>(g_part);
    const size_t rowq = NH / 4;
    float4 a = make_float4(0.f, 0.f, 0.f, 0.f);
    float4 c = make_float4(0.f, 0.f, 0.f, 0.f);
    #pragma unroll
    for (int s = 0; s < NSPL; s++) {
        float4 v1 = P[((size_t)s * (NE * NB) + l1) * rowq + tid];
        float4 v2 = P[((size_t)s * (NE * NB) + l2) * rowq + tid];
        a.x += v1.x; a.y += v1.y; a.z += v1.z; a.w += v1.w;
        c.x += v2.x; c.y += v2.y; c.z += v2.z; c.w += v2.w;
    }
    const float4 bb1 = reinterpret_cast<const float4*>(b2 + (size_t)e1 * NH)[tid];
    const float4 bb2 = reinterpret_cast<const float4*>(b2 + (size_t)e2 * NH)[tid];
    float4 o;
    o.x = s1 * (a.x + bb1.x) + s2 * (c.x + bb2.x);
    o.y = s1 * (a.y + bb1.y) + s2 * (c.y + bb2.y);
    o.z = s1 * (a.z + bb1.z) + s2 * (c.z + bb2.z);
    o.w = s1 * (a.w + bb1.w) + s2 * (c.w + bb2.w);
    reinterpret_cast<float4*>(y + (size_t)b * NH)[tid] = o;
}

// ---------------- aux loss ----------------
__global__ void aux_kernel(float* __restrict__ out) {
    float s = 0.f;
    #pragma unroll
    for (int e = 0; e < NE; e++)
        s += (g_psum[e] / (float)NB) * (g_rsum[e] / (float)NB);
    out[(size_t)NB * NH] = s * (float)NE;
}

// ---------------- launch ----------------
extern "C" void kernel_launch(void* const* d_in, const int* in_sizes, int n_in,
                              void* d_out, int out_size) {
    const float* x  = (const float*)d_in[0];
    const float* gw = (const float*)d_in[1];
    const float* gb = (const float*)d_in[2];
    const float* w1 = (const float*)d_in[3];
    const float* b1 = (const float*)d_in[4];
    const float* w2 = (const float*)d_in[5];
    const float* b2 = (const float*)d_in[6];
    float* y = (float*)d_out;

    const int SMEM_BYTES = 4 * 10240 + 4 * 8704;   // 75776
    cudaFuncSetAttribute(moe_gemm<NH, ND, false, 1>,
                         cudaFuncAttributeMaxDynamicSharedMemorySize, SMEM_BYTES);
    cudaFuncSetAttribute(moe_gemm<ND / NSPL, NH, true, NSPL>,
                         cudaFuncAttributeMaxDynamicSharedMemorySize, SMEM_BYTES);

    const size_t nw = (size_t)NE * NH * ND / 4;

    prep_w1_kernel<<<(unsigned)((nw + 255) / 256), 256>>>(w1);              // #1
    prep_w2_kernel<<<(unsigned)((nw + 255) / 256), 256>>>(w2, x);           // #2
    gate_kernel<<<NB, 256>>>(x, gw, gb);                                    // #3
    moe_gemm<NH, ND, false, 1>                                              // #4 (profiled)
        <<<dim3(ND / 128, NB / 128, NE), 256, SMEM_BYTES>>>(b1);
    moe_gemm<ND / NSPL, NH, true, NSPL>                                     // #5
        <<<dim3(NH / 128, NB / 128, NE * NSPL), 256, SMEM_BYTES>>>(b2);
    combine_kernel<<<NB, 256>>>(b2, y);                                     // #6
    aux_kernel<<<1, 1>>>(y);                                                // #7
}

// round 10
// speedup vs baseline: 1.4532x; 1.4532x over previous
#include <cuda_runtime.h>
#include <cuda_fp16.h>
#include <cstdint>

#define NB 4096   // tokens
#define NH 1024   // hidden
#define ND 4096   // expert dim
#define NE 8      // experts
#define NSPL 4    // split-K for GEMM2 (partials via STG, no atomics)

// ---------------- scratch (__device__ globals: allocation-guard safe) ----------------
__device__ __half g_xh [(size_t)NB * NH];              //   8 MB
__device__ __half g_w1h[(size_t)NE * NH * ND];         //  64 MB
__device__ __half g_w2h[(size_t)NE * ND * NH];         //  64 MB
__device__ __half g_h  [(size_t)NE * NB * ND];         // 256 MB
__device__ float  g_part[(size_t)NSPL * NE * NB * NH]; // 512 MB split partials
__device__ int    g_cnt[NE];
__device__ int    g_idx[NE * NB];
__device__ float  g_scale[NE * NB];
__device__ int    g_loc[NB * 2];
__device__ float  g_psum[NE];
__device__ float  g_rsum[NE];

// ---------------- helpers ----------------
__device__ __forceinline__ uint32_t smem_u32(const void* p) {
    return (uint32_t)__cvta_generic_to_shared(p);
}
__device__ __forceinline__ void cp16(uint32_t smem, const void* gmem) {
    asm volatile("cp.async.cg.shared.global [%0], [%1], 16;\n"
                 :: "r"(smem), "l"(gmem) : "memory");
}

// ---------------- prep: w1 + x fp32->fp16 + zero routing state (launch #1) ----------------
__global__ void prep_w1_kernel(const float* __restrict__ w1,
                               const float* __restrict__ x) {
    size_t i = (size_t)blockIdx.x * blockDim.x + threadIdx.x;
    if (i < (size_t)NE * NH * ND / 4) {
        float4 v = reinterpret_cast<const float4*>(w1)[i];
        __half2* d2 = reinterpret_cast<__half2*>(g_w1h) + i * 2;
        d2[0] = __floats2half2_rn(v.x, v.y);
        d2[1] = __floats2half2_rn(v.z, v.w);
    }
    if (i < (size_t)NB * NH / 4) {
        float4 v = reinterpret_cast<const float4*>(x)[i];
        __half2* d2 = reinterpret_cast<__half2*>(g_xh) + i * 2;
        d2[0] = __floats2half2_rn(v.x, v.y);
        d2[1] = __floats2half2_rn(v.z, v.w);
    }
    if (i < NE) { g_cnt[i] = 0; g_psum[i] = 0.f; g_rsum[i] = 0.f; }
}

// ---------------- gating (launch #2) ----------------
__global__ void gate_kernel(const float* __restrict__ x,
                            const float* __restrict__ gw,
                            const float* __restrict__ gb) {
    __shared__ float sx[NH];
    __shared__ float slog[NE];
    const int b = blockIdx.x, tid = threadIdx.x;
    for (int i = tid; i < NH; i += 256) sx[i] = x[(size_t)b * NH + i];
    __syncthreads();
    const int w = tid >> 5, lane = tid & 31;
    float s = 0.f;
    for (int i = lane; i < NH; i += 32) s += sx[i] * gw[i * NE + w];
    #pragma unroll
    for (int o = 16; o; o >>= 1) s += __shfl_xor_sync(0xffffffffu, s, o);
    if (lane == 0) slog[w] = s + gb[w];
    __syncthreads();
    if (tid == 0) {
        float p[NE];
        float mx = slog[0];
        #pragma unroll
        for (int e = 1; e < NE; e++) mx = fmaxf(mx, slog[e]);
        float den = 0.f;
        #pragma unroll
        for (int e = 0; e < NE; e++) { p[e] = expf(slog[e] - mx); den += p[e]; }
        float inv = 1.f / den;
        #pragma unroll
        for (int e = 0; e < NE; e++) p[e] *= inv;
        int e1 = 0; float p1 = p[0];
        #pragma unroll
        for (int e = 1; e < NE; e++) if (p[e] > p1) { p1 = p[e]; e1 = e; }
        int e2 = (e1 == 0) ? 1 : 0; float p2 = p[e2];
        #pragma unroll
        for (int e = 0; e < NE; e++)
            if (e != e1 && p[e] > p2) { p2 = p[e]; e2 = e; }
        int pos = atomicAdd(&g_cnt[e1], 1);
        g_idx[e1 * NB + pos] = b; g_scale[e1 * NB + pos] = p1 * 0.5f;
        g_loc[b * 2 + 0] = e1 * NB + pos;
        pos = atomicAdd(&g_cnt[e2], 1);
        g_idx[e2 * NB + pos] = b; g_scale[e2 * NB + pos] = p2 * 0.5f;
        g_loc[b * 2 + 1] = e2 * NB + pos;
        #pragma unroll
        for (int e = 0; e < NE; e++) atomicAdd(&g_psum[e], p[e]);
        atomicAdd(&g_rsum[e1], 1.f);
        atomicAdd(&g_rsum[e2], 1.f);
    }
}

// ---------------- grouped GEMM (R8 mainloop, FROZEN): CTA 128x128, 256 thr, warp 32x64,
//                  K-chunk 32, 3-stage ring, 1 sync/chunk ----------------
// smem/stage: A 128 x 80B = 10240, B 32 x 272B = 8704; 3 stages = 56832
// ISB==false: h = relu(Xg @ W1 + b1); idle CTAs (m0>=cnt) convert w2 fp32->fp16 instead
// ISB==true : g_part[split][e-slot] = Xh @ W2 chunk   (plain STG; combine reduces)
template<int KLEN, int NDIM, bool ISB, int NSPLIT>
__global__ void __launch_bounds__(256, 2)
moe_gemm(const float* __restrict__ bias, const float* __restrict__ w2src) {
    constexpr int KT   = KLEN / 32;
    constexpr int ASTG = 10240, BSTG = 8704;
    const int zi    = blockIdx.z;
    const int e     = (NSPLIT == 1) ? zi : (zi >> 2);
    const int split = (NSPLIT == 1) ? 0  : (zi & 3);
    const int cnt = g_cnt[e];
    const int m0  = blockIdx.y * 128;
    const int tid = threadIdx.x;

    if (m0 >= cnt) {
        if (ISB) return;
        // ---- idle CTA: convert a disjoint slice of w2 fp32 -> fp16 ----
        // rank among idle CTAs, deterministic from g_cnt (gridDim.y == 32, gridDim.x == 32)
        int base = 0, T = 0, rrow = 0;
        #pragma unroll
        for (int ee = 0; ee < NE; ee++) {
            const int ya   = (g_cnt[ee] + 127) >> 7;   // active y-blocks for expert ee
            const int idle = 32 - ya;
            if (ee < e) base += idle;
            if (ee == e) rrow = blockIdx.y - ya;
            T += idle;
        }
        const int r  = (base + rrow) * 32 + blockIdx.x;   // this CTA's idle rank
        const int Tc = T * 32;                            // total idle CTAs
        const size_t N4 = (size_t)NE * ND * NH / 4;       // float4 groups in w2
        const size_t chunk = (N4 + Tc - 1) / (size_t)Tc;
        const size_t lo = (size_t)r * chunk;
        const size_t hi = (lo + chunk < N4) ? lo + chunk : N4;
        for (size_t i = lo + tid; i < hi; i += 256) {
            float4 v = reinterpret_cast<const float4*>(w2src)[i];
            __half2* d2 = reinterpret_cast<__half2*>(g_w2h) + i * 2;
            d2[0] = __floats2half2_rn(v.x, v.y);
            d2[1] = __floats2half2_rn(v.z, v.w);
        }
        return;
    }

    const int n0    = blockIdx.x * 128;
    const int kbase = split * KLEN;

    extern __shared__ __align__(1024) char smem[];
    const uint32_t sA = smem_u32(smem);          // 3 * 10240
    const uint32_t sB = sA + 3 * ASTG;           // 3 * 8704

    // ---- gmem source pointers ----
    const int ar = tid >> 1;                      // A row (0..127), 2 threads/row
    const __half* Arow;
    if (ISB) {
        Arow = g_h + ((size_t)e * NB + m0 + ar) * ND + kbase;
    } else {
        const int s0  = m0 + ar;
        const int tok = g_idx[e * NB + (s0 < cnt ? s0 : 0)];
        Arow = g_xh + (size_t)tok * NH;
    }
    const __half* W = (ISB ? g_w2h : g_w1h)
                    + (size_t)e * (size_t)(KLEN * NSPLIT) * NDIM
                    + (size_t)kbase * NDIM + n0;
    const int br = tid >> 3;                      // B row (0..31), 8 threads/row

    auto load_stage = [&](int chunk, int s) {
        const uint32_t as = sA + s * ASTG + ar * 80;
        const __half* ag = Arow + chunk * 32;
        #pragma unroll
        for (int j = 0; j < 2; j++) {
            const int c4 = (tid & 1) * 2 + j;     // 16B col 0..3
            cp16(as + c4 * 16, ag + c4 * 8);
        }
        const uint32_t bs = sB + s * BSTG + br * 272;
        const __half* bg = W + (size_t)(chunk * 32 + br) * NDIM;
        #pragma unroll
        for (int j = 0; j < 2; j++) {
            const int cc = (tid & 7) * 2 + j;     // 16B col 0..15
            cp16(bs + cc * 16, bg + cc * 8);
        }
        asm volatile("cp.async.commit_group;" ::: "memory");
    };

    float acc[2][8][4];
    #pragma unroll
    for (int i = 0; i < 2; i++)
        #pragma unroll
        for (int j = 0; j < 8; j++)
            #pragma unroll
            for (int q = 0; q < 4; q++) acc[i][j][q] = 0.f;

    const int lane = tid & 31, warp = tid >> 5;
    const int wm = (warp & 3) * 32, wn = (warp >> 2) * 64;
    const uint32_t aoff = (uint32_t)(wm + (lane & 15)) * 80 + (lane >> 4) * 16;
    const uint32_t boff = (uint32_t)(lane & 15) * 272 + (uint32_t)(wn + (lane >> 4) * 8) * 2;

    load_stage(0, 0);
    load_stage(1, 1);

    for (int i = 0; i < KT; i++) {
        if (i < KT - 1) asm volatile("cp.async.wait_group 1;" ::: "memory");
        else            asm volatile("cp.async.wait_group 0;" ::: "memory");
        __syncthreads();
        if (i + 2 < KT) {
            int sp = i + 2; sp -= (sp / 3) * 3;
            load_stage(i + 2, sp);
        }
        int s = i; s -= (s / 3) * 3;
        const uint32_t ab = sA + s * ASTG + aoff;
        const uint32_t bb = sB + s * BSTG + boff;
        #pragma unroll
        for (int ks = 0; ks < 2; ks++) {
            uint32_t a[2][4], b[4][4];
            #pragma unroll
            for (int im = 0; im < 2; im++) {
                asm volatile("ldmatrix.sync.aligned.m8n8.x4.shared.b16 {%0,%1,%2,%3}, [%4];"
                             : "=r"(a[im][0]), "=r"(a[im][1]), "=r"(a[im][2]), "=r"(a[im][3])
                             : "r"(ab + im * 16 * 80 + ks * 32));
            }
            #pragma unroll
            for (int g = 0; g < 4; g++) {
                asm volatile("ldmatrix.sync.aligned.m8n8.x4.trans.shared.b16 {%0,%1,%2,%3}, [%4];"
                             : "=r"(b[g][0]), "=r"(b[g][1]), "=r"(b[g][2]), "=r"(b[g][3])
                             : "r"(bb + ks * 16 * 272 + g * 32));
            }
            #pragma unroll
            for (int im = 0; im < 2; im++)
                #pragma unroll
                for (int jn = 0; jn < 8; jn++) {
                    const uint32_t b0 = b[jn >> 1][(jn & 1) * 2 + 0];
                    const uint32_t b1 = b[jn >> 1][(jn & 1) * 2 + 1];
                    asm volatile("mma.sync.aligned.m16n8k16.row.col.f32.f16.f16.f32 "
                                 "{%0,%1,%2,%3},{%4,%5,%6,%7},{%8,%9},{%0,%1,%2,%3};"
                                 : "+f"(acc[im][jn][0]), "+f"(acc[im][jn][1]),
                                   "+f"(acc[im][jn][2]), "+f"(acc[im][jn][3])
                                 : "r"(a[im][0]), "r"(a[im][1]), "r"(a[im][2]), "r"(a[im][3]),
                                   "r"(b0), "r"(b1));
                }
        }
    }

    // ---- epilogue ----
    const int rb = lane >> 2;
    const int cb = (lane & 3) * 2;
    #pragma unroll
    for (int im = 0; im < 2; im++) {
        #pragma unroll
        for (int h = 0; h < 2; h++) {
            const int row  = wm + im * 16 + rb + h * 8;
            const int slot = m0 + row;
            if (slot >= cnt) continue;
            if (!ISB) {
                __half* drow = &g_h[((size_t)e * NB + slot) * ND + n0 + wn];
                #pragma unroll
                for (int jn = 0; jn < 8; jn++) {
                    const int gc = n0 + wn + jn * 8 + cb;
                    float v0 = fmaxf(acc[im][jn][h * 2 + 0] + bias[e * NDIM + gc],     0.f);
                    float v1 = fmaxf(acc[im][jn][h * 2 + 1] + bias[e * NDIM + gc + 1], 0.f);
                    *reinterpret_cast<__half2*>(drow + jn * 8 + cb) = __floats2half2_rn(v0, v1);
                }
            } else {
                float* prow = g_part + ((size_t)split * (NE * NB) + (size_t)e * NB + slot) * NH
                            + n0 + wn;
                #pragma unroll
                for (int jn = 0; jn < 8; jn++) {
                    float2 v = make_float2(acc[im][jn][h * 2 + 0], acc[im][jn][h * 2 + 1]);
                    *reinterpret_cast<float2*>(prow + jn * 8 + cb) = v;
                }
            }
        }
    }
}

// ---------------- combine: y[b] = sum_j sc_j * (sum_s P[s][loc_j] + b2[e_j]) ----------------
__global__ void __launch_bounds__(256)
combine_kernel(const float* __restrict__ b2, float* __restrict__ y) {
    const int b   = blockIdx.x;
    const int tid = threadIdx.x;                  // 256 threads x float4 -> 1024 cols
    const int l1 = g_loc[b * 2 + 0];
    const int l2 = g_loc[b * 2 + 1];
    const int e1 = l1 >> 12, e2 = l2 >> 12;       // NB = 4096 = 2^12
    const float s1 = g_scale[l1], s2 = g_scale[l2];

    const float4* P = reinterpret_cast<const float4*>(g_part);
    const size_t rowq = NH / 4;
    float4 a = make_float4(0.f, 0.f, 0.f, 0.f);
    float4 c = make_float4(0.f, 0.f, 0.f, 0.f);
    #pragma unroll
    for (int s = 0; s < NSPL; s++) {
        float4 v1 = P[((size_t)s * (NE * NB) + l1) * rowq + tid];
        float4 v2 = P[((size_t)s * (NE * NB) + l2) * rowq + tid];
        a.x += v1.x; a.y += v1.y; a.z += v1.z; a.w += v1.w;
        c.x += v2.x; c.y += v2.y; c.z += v2.z; c.w += v2.w;
    }
    const float4 bb1 = reinterpret_cast<const float4*>(b2 + (size_t)e1 * NH)[tid];
    const float4 bb2 = reinterpret_cast<const float4*>(b2 + (size_t)e2 * NH)[tid];
    float4 o;
    o.x = s1 * (a.x + bb1.x) + s2 * (c.x + bb2.x);
    o.y = s1 * (a.y + bb1.y) + s2 * (c.y + bb2.y);
    o.z = s1 * (a.z + bb1.z) + s2 * (c.z + bb2.z);
    o.w = s1 * (a.w + bb1.w) + s2 * (c.w + bb2.w);
    reinterpret_cast<float4*>(y + (size_t)b * NH)[tid] = o;
}

// ---------------- aux loss ----------------
__global__ void aux_kernel(float* __restrict__ out) {
    float s = 0.f;
    #pragma unroll
    for (int e = 0; e < NE; e++)
        s += (g_psum[e] / (float)NB) * (g_rsum[e] / (float)NB);
    out[(size_t)NB * NH] = s * (float)NE;
}

// ---------------- launch ----------------
extern "C" void kernel_launch(void* const* d_in, const int* in_sizes, int n_in,
                              void* d_out, int out_size) {
    const float* x  = (const float*)d_in[0];
    const float* gw = (const float*)d_in[1];
    const float* gb = (const float*)d_in[2];
    const float* w1 = (const float*)d_in[3];
    const float* b1 = (const float*)d_in[4];
    const float* w2 = (const float*)d_in[5];
    const float* b2 = (const float*)d_in[6];
    float* y = (float*)d_out;

    const int SMEM_BYTES = 3 * 10240 + 3 * 8704;   // 56832
    cudaFuncSetAttribute(moe_gemm<NH, ND, false, 1>,
                         cudaFuncAttributeMaxDynamicSharedMemorySize, SMEM_BYTES);
    cudaFuncSetAttribute(moe_gemm<ND / NSPL, NH, true, NSPL>,
                         cudaFuncAttributeMaxDynamicSharedMemorySize, SMEM_BYTES);

    const size_t nw = (size_t)NE * NH * ND / 4;

    prep_w1_kernel<<<(unsigned)((nw + 255) / 256), 256>>>(w1, x);           // #1
    gate_kernel<<<NB, 256>>>(x, gw, gb);                                    // #2
    moe_gemm<NH, ND, false, 1>                                              // #3 (idle CTAs convert w2)
        <<<dim3(ND / 128, NB / 128, NE), 256, SMEM_BYTES>>>(b1, w2);
    moe_gemm<ND / NSPL, NH, true, NSPL>                                     // #4 (profiled)
        <<<dim3(NH / 128, NB / 128, NE * NSPL), 256, SMEM_BYTES>>>(b2, nullptr);
    combine_kernel<<<NB, 256>>>(b2, y);                                     // #5
    aux_kernel<<<1, 1>>>(y);                                                // #6
}

// round 11
// speedup vs baseline: 1.4683x; 1.0103x over previous
#include <cuda_runtime.h>
#include <cuda_fp16.h>
#include <cstdint>

#define NB 4096   // tokens
#define NH 1024   // hidden
#define ND 4096   // expert dim
#define NE 8      // experts
#define NSPL 4    // split-K for GEMM2 (partials via STG, no atomics)

// ---------------- scratch (__device__ globals: allocation-guard safe) ----------------
__device__ __half g_xh [(size_t)NB * NH];              //   8 MB
__device__ __half g_w1h[(size_t)NE * NH * ND];         //  64 MB
__device__ __half g_w2h[(size_t)NE * ND * NH];         //  64 MB
__device__ __half g_h  [(size_t)NE * NB * ND];         // 256 MB
__device__ float  g_part[(size_t)NSPL * NE * NB * NH]; // 512 MB split partials
__device__ int    g_cnt[NE];
__device__ int    g_idx[NE * NB];
__device__ float  g_scale[NE * NB];
__device__ int    g_loc[NB * 2];
__device__ float  g_psum[NE];
__device__ float  g_rsum[NE];

// ---------------- helpers ----------------
__device__ __forceinline__ uint32_t smem_u32(const void* p) {
    return (uint32_t)__cvta_generic_to_shared(p);
}
__device__ __forceinline__ void cp16(uint32_t smem, const void* gmem) {
    asm volatile("cp.async.cg.shared.global [%0], [%1], 16;\n"
                 :: "r"(smem), "l"(gmem) : "memory");
}

// ---------------- prep: w1 + x fp32->fp16 + zero routing state (launch #1) ----------------
__global__ void prep_w1_kernel(const float* __restrict__ w1,
                               const float* __restrict__ x) {
    size_t i = (size_t)blockIdx.x * blockDim.x + threadIdx.x;
    if (i < (size_t)NE * NH * ND / 4) {
        float4 v = reinterpret_cast<const float4*>(w1)[i];
        __half2* d2 = reinterpret_cast<__half2*>(g_w1h) + i * 2;
        d2[0] = __floats2half2_rn(v.x, v.y);
        d2[1] = __floats2half2_rn(v.z, v.w);
    }
    if (i < (size_t)NB * NH / 4) {
        float4 v = reinterpret_cast<const float4*>(x)[i];
        __half2* d2 = reinterpret_cast<__half2*>(g_xh) + i * 2;
        d2[0] = __floats2half2_rn(v.x, v.y);
        d2[1] = __floats2half2_rn(v.z, v.w);
    }
    if (i < NE) { g_cnt[i] = 0; g_psum[i] = 0.f; g_rsum[i] = 0.f; }
}

// ---------------- gating + w2 conversion (launch #2) ----------------
// Gate logic is latency-bound (~10us over 4096 CTAs); the w2 fp32->fp16 conversion
// (96 MB of DRAM traffic) rides in the same kernel and hides the gate latency.
__global__ void gate_kernel(const float* __restrict__ x,
                            const float* __restrict__ gw,
                            const float* __restrict__ gb,
                            const float* __restrict__ w2) {
    __shared__ float sx[NH];
    __shared__ float slog[NE];
    const int b = blockIdx.x, tid = threadIdx.x;
    for (int i = tid; i < NH; i += 256) sx[i] = x[(size_t)b * NH + i];
    __syncthreads();
    const int w = tid >> 5, lane = tid & 31;
    float s = 0.f;
    for (int i = lane; i < NH; i += 32) s += sx[i] * gw[i * NE + w];
    #pragma unroll
    for (int o = 16; o; o >>= 1) s += __shfl_xor_sync(0xffffffffu, s, o);
    if (lane == 0) slog[w] = s + gb[w];
    __syncthreads();
    if (tid == 0) {
        float p[NE];
        float mx = slog[0];
        #pragma unroll
        for (int e = 1; e < NE; e++) mx = fmaxf(mx, slog[e]);
        float den = 0.f;
        #pragma unroll
        for (int e = 0; e < NE; e++) { p[e] = expf(slog[e] - mx); den += p[e]; }
        float inv = 1.f / den;
        #pragma unroll
        for (int e = 0; e < NE; e++) p[e] *= inv;
        int e1 = 0; float p1 = p[0];
        #pragma unroll
        for (int e = 1; e < NE; e++) if (p[e] > p1) { p1 = p[e]; e1 = e; }
        int e2 = (e1 == 0) ? 1 : 0; float p2 = p[e2];
        #pragma unroll
        for (int e = 0; e < NE; e++)
            if (e != e1 && p[e] > p2) { p2 = p[e]; e2 = e; }
        int pos = atomicAdd(&g_cnt[e1], 1);
        g_idx[e1 * NB + pos] = b; g_scale[e1 * NB + pos] = p1 * 0.5f;
        g_loc[b * 2 + 0] = e1 * NB + pos;
        pos = atomicAdd(&g_cnt[e2], 1);
        g_idx[e2 * NB + pos] = b; g_scale[e2 * NB + pos] = p2 * 0.5f;
        g_loc[b * 2 + 1] = e2 * NB + pos;
        #pragma unroll
        for (int e = 0; e < NE; e++) atomicAdd(&g_psum[e], p[e]);
        atomicAdd(&g_rsum[e1], 1.f);
        atomicAdd(&g_rsum[e2], 1.f);
    }
    // ---- w2 fp32 -> fp16 (grid-stride over 8M float4 groups) ----
    const size_t N4 = (size_t)NE * ND * NH / 4;
    const size_t stride = (size_t)gridDim.x * 256;
    for (size_t i = (size_t)blockIdx.x * 256 + tid; i < N4; i += stride) {
        float4 v = reinterpret_cast<const float4*>(w2)[i];
        __half2* d2 = reinterpret_cast<__half2*>(g_w2h) + i * 2;
        d2[0] = __floats2half2_rn(v.x, v.y);
        d2[1] = __floats2half2_rn(v.z, v.w);
    }
}

// ---------------- grouped GEMM (R8 mainloop, FROZEN): CTA 128x128, 256 thr, warp 32x64,
//                  K-chunk 32, 3-stage ring, 1 sync/chunk ----------------
// smem/stage: A 128 x 80B = 10240, B 32 x 272B = 8704; 3 stages = 56832
// ISB==false: h = relu(Xg @ W1 + b1)
// ISB==true : g_part[split][e-slot] = Xh @ W2 chunk   (plain STG; combine reduces)
template<int KLEN, int NDIM, bool ISB, int NSPLIT>
__global__ void __launch_bounds__(256, 2)
moe_gemm(const float* __restrict__ bias) {
    constexpr int KT   = KLEN / 32;
    constexpr int ASTG = 10240, BSTG = 8704;
    const int zi    = blockIdx.z;
    const int e     = (NSPLIT == 1) ? zi : (zi >> 2);
    const int split = (NSPLIT == 1) ? 0  : (zi & 3);
    const int cnt = g_cnt[e];
    const int m0  = blockIdx.y * 128;
    if (m0 >= cnt) return;
    const int n0    = blockIdx.x * 128;
    const int kbase = split * KLEN;
    const int tid   = threadIdx.x;

    extern __shared__ __align__(1024) char smem[];
    const uint32_t sA = smem_u32(smem);          // 3 * 10240
    const uint32_t sB = sA + 3 * ASTG;           // 3 * 8704

    // ---- gmem source pointers ----
    const int ar = tid >> 1;                      // A row (0..127), 2 threads/row
    const __half* Arow;
    if (ISB) {
        Arow = g_h + ((size_t)e * NB + m0 + ar) * ND + kbase;
    } else {
        const int s0  = m0 + ar;
        const int tok = g_idx[e * NB + (s0 < cnt ? s0 : 0)];
        Arow = g_xh + (size_t)tok * NH;
    }
    const __half* W = (ISB ? g_w2h : g_w1h)
                    + (size_t)e * (size_t)(KLEN * NSPLIT) * NDIM
                    + (size_t)kbase * NDIM + n0;
    const int br = tid >> 3;                      // B row (0..31), 8 threads/row

    auto load_stage = [&](int chunk, int s) {
        const uint32_t as = sA + s * ASTG + ar * 80;
        const __half* ag = Arow + chunk * 32;
        #pragma unroll
        for (int j = 0; j < 2; j++) {
            const int c4 = (tid & 1) * 2 + j;     // 16B col 0..3
            cp16(as + c4 * 16, ag + c4 * 8);
        }
        const uint32_t bs = sB + s * BSTG + br * 272;
        const __half* bg = W + (size_t)(chunk * 32 + br) * NDIM;
        #pragma unroll
        for (int j = 0; j < 2; j++) {
            const int cc = (tid & 7) * 2 + j;     // 16B col 0..15
            cp16(bs + cc * 16, bg + cc * 8);
        }
        asm volatile("cp.async.commit_group;" ::: "memory");
    };

    float acc[2][8][4];
    #pragma unroll
    for (int i = 0; i < 2; i++)
        #pragma unroll
        for (int j = 0; j < 8; j++)
            #pragma unroll
            for (int q = 0; q < 4; q++) acc[i][j][q] = 0.f;

    const int lane = tid & 31, warp = tid >> 5;
    const int wm = (warp & 3) * 32, wn = (warp >> 2) * 64;
    const uint32_t aoff = (uint32_t)(wm + (lane & 15)) * 80 + (lane >> 4) * 16;
    const uint32_t boff = (uint32_t)(lane & 15) * 272 + (uint32_t)(wn + (lane >> 4) * 8) * 2;

    load_stage(0, 0);
    load_stage(1, 1);

    for (int i = 0; i < KT; i++) {
        if (i < KT - 1) asm volatile("cp.async.wait_group 1;" ::: "memory");
        else            asm volatile("cp.async.wait_group 0;" ::: "memory");
        __syncthreads();
        if (i + 2 < KT) {
            int sp = i + 2; sp -= (sp / 3) * 3;
            load_stage(i + 2, sp);
        }
        int s = i; s -= (s / 3) * 3;
        const uint32_t ab = sA + s * ASTG + aoff;
        const uint32_t bb = sB + s * BSTG + boff;
        #pragma unroll
        for (int ks = 0; ks < 2; ks++) {
            uint32_t a[2][4], b[4][4];
            #pragma unroll
            for (int im = 0; im < 2; im++) {
                asm volatile("ldmatrix.sync.aligned.m8n8.x4.shared.b16 {%0,%1,%2,%3}, [%4];"
                             : "=r"(a[im][0]), "=r"(a[im][1]), "=r"(a[im][2]), "=r"(a[im][3])
                             : "r"(ab + im * 16 * 80 + ks * 32));
            }
            #pragma unroll
            for (int g = 0; g < 4; g++) {
                asm volatile("ldmatrix.sync.aligned.m8n8.x4.trans.shared.b16 {%0,%1,%2,%3}, [%4];"
                             : "=r"(b[g][0]), "=r"(b[g][1]), "=r"(b[g][2]), "=r"(b[g][3])
                             : "r"(bb + ks * 16 * 272 + g * 32));
            }
            #pragma unroll
            for (int im = 0; im < 2; im++)
                #pragma unroll
                for (int jn = 0; jn < 8; jn++) {
                    const uint32_t b0 = b[jn >> 1][(jn & 1) * 2 + 0];
                    const uint32_t b1 = b[jn >> 1][(jn & 1) * 2 + 1];
                    asm volatile("mma.sync.aligned.m16n8k16.row.col.f32.f16.f16.f32 "
                                 "{%0,%1,%2,%3},{%4,%5,%6,%7},{%8,%9},{%0,%1,%2,%3};"
                                 : "+f"(acc[im][jn][0]), "+f"(acc[im][jn][1]),
                                   "+f"(acc[im][jn][2]), "+f"(acc[im][jn][3])
                                 : "r"(a[im][0]), "r"(a[im][1]), "r"(a[im][2]), "r"(a[im][3]),
                                   "r"(b0), "r"(b1));
                }
        }
    }

    // ---- epilogue ----
    const int rb = lane >> 2;
    const int cb = (lane & 3) * 2;
    #pragma unroll
    for (int im = 0; im < 2; im++) {
        #pragma unroll
        for (int h = 0; h < 2; h++) {
            const int row  = wm + im * 16 + rb + h * 8;
            const int slot = m0 + row;
            if (slot >= cnt) continue;
            if (!ISB) {
                __half* drow = &g_h[((size_t)e * NB + slot) * ND + n0 + wn];
                #pragma unroll
                for (int jn = 0; jn < 8; jn++) {
                    const int gc = n0 + wn + jn * 8 + cb;
                    float v0 = fmaxf(acc[im][jn][h * 2 + 0] + bias[e * NDIM + gc],     0.f);
                    float v1 = fmaxf(acc[im][jn][h * 2 + 1] + bias[e * NDIM + gc + 1], 0.f);
                    *reinterpret_cast<__half2*>(drow + jn * 8 + cb) = __floats2half2_rn(v0, v1);
                }
            } else {
                float* prow = g_part + ((size_t)split * (NE * NB) + (size_t)e * NB + slot) * NH
                            + n0 + wn;
                #pragma unroll
                for (int jn = 0; jn < 8; jn++) {
                    float2 v = make_float2(acc[im][jn][h * 2 + 0], acc[im][jn][h * 2 + 1]);
                    *reinterpret_cast<float2*>(prow + jn * 8 + cb) = v;
                }
            }
        }
    }
}

// ---------------- combine + aux: y[b] = sum_j sc_j * (sum_s P[s][loc_j] + b2[e_j]) ----------------
__global__ void __launch_bounds__(256)
combine_kernel(const float* __restrict__ b2, float* __restrict__ y) {
    const int b   = blockIdx.x;
    const int tid = threadIdx.x;                  // 256 threads x float4 -> 1024 cols
    const int l1 = g_loc[b * 2 + 0];
    const int l2 = g_loc[b * 2 + 1];
    const int e1 = l1 >> 12, e2 = l2 >> 12;       // NB = 4096 = 2^12
    const float s1 = g_scale[l1], s2 = g_scale[l2];

    const float4* P = reinterpret_cast<const float4*>(g_part);
    const size_t rowq = NH / 4;
    float4 a = make_float4(0.f, 0.f, 0.f, 0.f);
    float4 c = make_float4(0.f, 0.f, 0.f, 0.f);
    #pragma unroll
    for (int s = 0; s < NSPL; s++) {
        float4 v1 = P[((size_t)s * (NE * NB) + l1) * rowq + tid];
        float4 v2 = P[((size_t)s * (NE * NB) + l2) * rowq + tid];
        a.x += v1.x; a.y += v1.y; a.z += v1.z; a.w += v1.w;
        c.x += v2.x; c.y += v2.y; c.z += v2.z; c.w += v2.w;
    }
    const float4 bb1 = reinterpret_cast<const float4*>(b2 + (size_t)e1 * NH)[tid];
    const float4 bb2 = reinterpret_cast<const float4*>(b2 + (size_t)e2 * NH)[tid];
    float4 o;
    o.x = s1 * (a.x + bb1.x) + s2 * (c.x + bb2.x);
    o.y = s1 * (a.y + bb1.y) + s2 * (c.y + bb2.y);
    o.z = s1 * (a.z + bb1.z) + s2 * (c.z + bb2.z);
    o.w = s1 * (a.w + bb1.w) + s2 * (c.w + bb2.w);
    reinterpret_cast<float4*>(y + (size_t)b * NH)[tid] = o;

    // ---- aux loss (block 0 only; g_psum/g_rsum finalized in gate kernel) ----
    if (b == 0 && tid == 0) {
        float s = 0.f;
        #pragma unroll
        for (int e = 0; e < NE; e++)
            s += (g_psum[e] / (float)NB) * (g_rsum[e] / (float)NB);
        y[(size_t)NB * NH] = s * (float)NE;
    }
}

// ---------------- launch ----------------
extern "C" void kernel_launch(void* const* d_in, const int* in_sizes, int n_in,
                              void* d_out, int out_size) {
    const float* x  = (const float*)d_in[0];
    const float* gw = (const float*)d_in[1];
    const float* gb = (const float*)d_in[2];
    const float* w1 = (const float*)d_in[3];
    const float* b1 = (const float*)d_in[4];
    const float* w2 = (const float*)d_in[5];
    const float* b2 = (const float*)d_in[6];
    float* y = (float*)d_out;

    const int SMEM_BYTES = 3 * 10240 + 3 * 8704;   // 56832
    cudaFuncSetAttribute(moe_gemm<NH, ND, false, 1>,
                         cudaFuncAttributeMaxDynamicSharedMemorySize, SMEM_BYTES);
    cudaFuncSetAttribute(moe_gemm<ND / NSPL, NH, true, NSPL>,
                         cudaFuncAttributeMaxDynamicSharedMemorySize, SMEM_BYTES);

    const size_t nw = (size_t)NE * NH * ND / 4;

    prep_w1_kernel<<<(unsigned)((nw + 255) / 256), 256>>>(w1, x);           // #1
    gate_kernel<<<NB, 256>>>(x, gw, gb, w2);                                // #2 (gate + w2 convert)
    moe_gemm<NH, ND, false, 1>                                              // #3
        <<<dim3(ND / 128, NB / 128, NE), 256, SMEM_BYTES>>>(b1);
    moe_gemm<ND / NSPL, NH, true, NSPL>                                     // #4 (profiled)
        <<<dim3(NH / 128, NB / 128, NE * NSPL), 256, SMEM_BYTES>>>(b2);
    combine_kernel<<<NB, 256>>>(b2, y);                                     // #5 (+aux)
    aux_kernel_unused:;
}

// round 12
// speedup vs baseline: 1.4684x; 1.0001x over previous
#include <cuda_runtime.h>
#include <cuda_fp16.h>
#include <cstdint>

#define NB 4096   // tokens
#define NH 1024   // hidden
#define ND 4096   // expert dim
#define NE 8      // experts
#define NSPL 4    // split-K for GEMM2 (fp16 partials via STG, no atomics)

// ---------------- scratch (__device__ globals: allocation-guard safe) ----------------
__device__ __half g_xh [(size_t)NB * NH];              //   8 MB
__device__ __half g_w1h[(size_t)NE * NH * ND];         //  64 MB
__device__ __half g_w2h[(size_t)NE * ND * NH];         //  64 MB
__device__ __half g_h  [(size_t)NE * NB * ND];         // 256 MB
__device__ __half g_part[(size_t)NSPL * NE * NB * NH]; // 256 MB fp16 split partials
__device__ int    g_cnt[NE];
__device__ int    g_idx[NE * NB];
__device__ float  g_scale[NE * NB];
__device__ int    g_loc[NB * 2];
__device__ float  g_psum[NE];
__device__ float  g_rsum[NE];

// ---------------- helpers ----------------
__device__ __forceinline__ uint32_t smem_u32(const void* p) {
    return (uint32_t)__cvta_generic_to_shared(p);
}
__device__ __forceinline__ void cp16(uint32_t smem, const void* gmem) {
    asm volatile("cp.async.cg.shared.global [%0], [%1], 16;\n"
                 :: "r"(smem), "l"(gmem) : "memory");
}

// ---------------- fused prep: w1 + w2 + x fp32->fp16, zero routing state (launch #1) ----------------
__global__ void __launch_bounds__(256)
prep_kernel(const float* __restrict__ w1, const float* __restrict__ w2,
            const float* __restrict__ x) {
    const size_t stride = (size_t)gridDim.x * 256;
    const size_t tid0   = (size_t)blockIdx.x * 256 + threadIdx.x;
    const size_t NW = (size_t)NE * NH * ND / 4;        // 8M float4 groups each for w1/w2
    const size_t NX = (size_t)NB * NH / 4;             // 1M for x
    for (size_t i = tid0; i < NW; i += stride) {
        float4 v = reinterpret_cast<const float4*>(w1)[i];
        __half2* d2 = reinterpret_cast<__half2*>(g_w1h) + i * 2;
        d2[0] = __floats2half2_rn(v.x, v.y);
        d2[1] = __floats2half2_rn(v.z, v.w);
    }
    for (size_t i = tid0; i < NW; i += stride) {
        float4 v = reinterpret_cast<const float4*>(w2)[i];
        __half2* d2 = reinterpret_cast<__half2*>(g_w2h) + i * 2;
        d2[0] = __floats2half2_rn(v.x, v.y);
        d2[1] = __floats2half2_rn(v.z, v.w);
    }
    for (size_t i = tid0; i < NX; i += stride) {
        float4 v = reinterpret_cast<const float4*>(x)[i];
        __half2* d2 = reinterpret_cast<__half2*>(g_xh) + i * 2;
        d2[0] = __floats2half2_rn(v.x, v.y);
        d2[1] = __floats2half2_rn(v.z, v.w);
    }
    if (tid0 < NE) { g_cnt[tid0] = 0; g_psum[tid0] = 0.f; g_rsum[tid0] = 0.f; }
}

// ---------------- gating (launch #2) ----------------
__global__ void gate_kernel(const float* __restrict__ x,
                            const float* __restrict__ gw,
                            const float* __restrict__ gb) {
    __shared__ float sx[NH];
    __shared__ float slog[NE];
    const int b = blockIdx.x, tid = threadIdx.x;
    for (int i = tid; i < NH; i += 256) sx[i] = x[(size_t)b * NH + i];
    __syncthreads();
    const int w = tid >> 5, lane = tid & 31;
    float s = 0.f;
    for (int i = lane; i < NH; i += 32) s += sx[i] * gw[i * NE + w];
    #pragma unroll
    for (int o = 16; o; o >>= 1) s += __shfl_xor_sync(0xffffffffu, s, o);
    if (lane == 0) slog[w] = s + gb[w];
    __syncthreads();
    if (tid == 0) {
        float p[NE];
        float mx = slog[0];
        #pragma unroll
        for (int e = 1; e < NE; e++) mx = fmaxf(mx, slog[e]);
        float den = 0.f;
        #pragma unroll
        for (int e = 0; e < NE; e++) { p[e] = expf(slog[e] - mx); den += p[e]; }
        float inv = 1.f / den;
        #pragma unroll
        for (int e = 0; e < NE; e++) p[e] *= inv;
        int e1 = 0; float p1 = p[0];
        #pragma unroll
        for (int e = 1; e < NE; e++) if (p[e] > p1) { p1 = p[e]; e1 = e; }
        int e2 = (e1 == 0) ? 1 : 0; float p2 = p[e2];
        #pragma unroll
        for (int e = 0; e < NE; e++)
            if (e != e1 && p[e] > p2) { p2 = p[e]; e2 = e; }
        int pos = atomicAdd(&g_cnt[e1], 1);
        g_idx[e1 * NB + pos] = b; g_scale[e1 * NB + pos] = p1 * 0.5f;
        g_loc[b * 2 + 0] = e1 * NB + pos;
        pos = atomicAdd(&g_cnt[e2], 1);
        g_idx[e2 * NB + pos] = b; g_scale[e2 * NB + pos] = p2 * 0.5f;
        g_loc[b * 2 + 1] = e2 * NB + pos;
        #pragma unroll
        for (int e = 0; e < NE; e++) atomicAdd(&g_psum[e], p[e]);
        atomicAdd(&g_rsum[e1], 1.f);
        atomicAdd(&g_rsum[e2], 1.f);
    }
}

// ---------------- grouped GEMM (R8 mainloop, FROZEN): CTA 128x128, 256 thr, warp 32x64,
//                  K-chunk 32, 3-stage ring, 1 sync/chunk ----------------
// smem/stage: A 128 x 80B = 10240, B 32 x 272B = 8704; 3 stages = 56832
// ISB==false: h = relu(Xg @ W1 + b1)
// ISB==true : g_part[split][e-slot] = Xh @ W2 chunk   (fp16 STG; combine reduces)
template<int KLEN, int NDIM, bool ISB, int NSPLIT>
__global__ void __launch_bounds__(256, 2)
moe_gemm(const float* __restrict__ bias) {
    constexpr int KT   = KLEN / 32;
    constexpr int ASTG = 10240, BSTG = 8704;
    const int zi    = blockIdx.z;
    const int e     = (NSPLIT == 1) ? zi : (zi >> 2);
    const int split = (NSPLIT == 1) ? 0  : (zi & 3);
    const int cnt = g_cnt[e];
    const int m0  = blockIdx.y * 128;
    if (m0 >= cnt) return;
    const int n0    = blockIdx.x * 128;
    const int kbase = split * KLEN;
    const int tid   = threadIdx.x;

    extern __shared__ __align__(1024) char smem[];
    const uint32_t sA = smem_u32(smem);          // 3 * 10240
    const uint32_t sB = sA + 3 * ASTG;           // 3 * 8704

    // ---- gmem source pointers ----
    const int ar = tid >> 1;                      // A row (0..127), 2 threads/row
    const __half* Arow;
    if (ISB) {
        Arow = g_h + ((size_t)e * NB + m0 + ar) * ND + kbase;
    } else {
        const int s0  = m0 + ar;
        const int tok = g_idx[e * NB + (s0 < cnt ? s0 : 0)];
        Arow = g_xh + (size_t)tok * NH;
    }
    const __half* W = (ISB ? g_w2h : g_w1h)
                    + (size_t)e * (size_t)(KLEN * NSPLIT) * NDIM
                    + (size_t)kbase * NDIM + n0;
    const int br = tid >> 3;                      // B row (0..31), 8 threads/row

    auto load_stage = [&](int chunk, int s) {
        const uint32_t as = sA + s * ASTG + ar * 80;
        const __half* ag = Arow + chunk * 32;
        #pragma unroll
        for (int j = 0; j < 2; j++) {
            const int c4 = (tid & 1) * 2 + j;     // 16B col 0..3
            cp16(as + c4 * 16, ag + c4 * 8);
        }
        const uint32_t bs = sB + s * BSTG + br * 272;
        const __half* bg = W + (size_t)(chunk * 32 + br) * NDIM;
        #pragma unroll
        for (int j = 0; j < 2; j++) {
            const int cc = (tid & 7) * 2 + j;     // 16B col 0..15
            cp16(bs + cc * 16, bg + cc * 8);
        }
        asm volatile("cp.async.commit_group;" ::: "memory");
    };

    float acc[2][8][4];
    #pragma unroll
    for (int i = 0; i < 2; i++)
        #pragma unroll
        for (int j = 0; j < 8; j++)
            #pragma unroll
            for (int q = 0; q < 4; q++) acc[i][j][q] = 0.f;

    const int lane = tid & 31, warp = tid >> 5;
    const int wm = (warp & 3) * 32, wn = (warp >> 2) * 64;
    const uint32_t aoff = (uint32_t)(wm + (lane & 15)) * 80 + (lane >> 4) * 16;
    const uint32_t boff = (uint32_t)(lane & 15) * 272 + (uint32_t)(wn + (lane >> 4) * 8) * 2;

    load_stage(0, 0);
    load_stage(1, 1);

    for (int i = 0; i < KT; i++) {
        if (i < KT - 1) asm volatile("cp.async.wait_group 1;" ::: "memory");
        else            asm volatile("cp.async.wait_group 0;" ::: "memory");
        __syncthreads();
        if (i + 2 < KT) {
            int sp = i + 2; sp -= (sp / 3) * 3;
            load_stage(i + 2, sp);
        }
        int s = i; s -= (s / 3) * 3;
        const uint32_t ab = sA + s * ASTG + aoff;
        const uint32_t bb = sB + s * BSTG + boff;
        #pragma unroll
        for (int ks = 0; ks < 2; ks++) {
            uint32_t a[2][4], b[4][4];
            #pragma unroll
            for (int im = 0; im < 2; im++) {
                asm volatile("ldmatrix.sync.aligned.m8n8.x4.shared.b16 {%0,%1,%2,%3}, [%4];"
                             : "=r"(a[im][0]), "=r"(a[im][1]), "=r"(a[im][2]), "=r"(a[im][3])
                             : "r"(ab + im * 16 * 80 + ks * 32));
            }
            #pragma unroll
            for (int g = 0; g < 4; g++) {
                asm volatile("ldmatrix.sync.aligned.m8n8.x4.trans.shared.b16 {%0,%1,%2,%3}, [%4];"
                             : "=r"(b[g][0]), "=r"(b[g][1]), "=r"(b[g][2]), "=r"(b[g][3])
                             : "r"(bb + ks * 16 * 272 + g * 32));
            }
            #pragma unroll
            for (int im = 0; im < 2; im++)
                #pragma unroll
                for (int jn = 0; jn < 8; jn++) {
                    const uint32_t b0 = b[jn >> 1][(jn & 1) * 2 + 0];
                    const uint32_t b1 = b[jn >> 1][(jn & 1) * 2 + 1];
                    asm volatile("mma.sync.aligned.m16n8k16.row.col.f32.f16.f16.f32 "
                                 "{%0,%1,%2,%3},{%4,%5,%6,%7},{%8,%9},{%0,%1,%2,%3};"
                                 : "+f"(acc[im][jn][0]), "+f"(acc[im][jn][1]),
                                   "+f"(acc[im][jn][2]), "+f"(acc[im][jn][3])
                                 : "r"(a[im][0]), "r"(a[im][1]), "r"(a[im][2]), "r"(a[im][3]),
                                   "r"(b0), "r"(b1));
                }
        }
    }

    // ---- epilogue ----
    const int rb = lane >> 2;
    const int cb = (lane & 3) * 2;
    #pragma unroll
    for (int im = 0; im < 2; im++) {
        #pragma unroll
        for (int h = 0; h < 2; h++) {
            const int row  = wm + im * 16 + rb + h * 8;
            const int slot = m0 + row;
            if (slot >= cnt) continue;
            if (!ISB) {
                __half* drow = &g_h[((size_t)e * NB + slot) * ND + n0 + wn];
                #pragma unroll
                for (int jn = 0; jn < 8; jn++) {
                    const int gc = n0 + wn + jn * 8 + cb;
                    float v0 = fmaxf(acc[im][jn][h * 2 + 0] + bias[e * NDIM + gc],     0.f);
                    float v1 = fmaxf(acc[im][jn][h * 2 + 1] + bias[e * NDIM + gc + 1], 0.f);
                    *reinterpret_cast<__half2*>(drow + jn * 8 + cb) = __floats2half2_rn(v0, v1);
                }
            } else {
                __half* prow = g_part + ((size_t)split * (NE * NB) + (size_t)e * NB + slot) * NH
                             + n0 + wn;
                #pragma unroll
                for (int jn = 0; jn < 8; jn++) {
                    *reinterpret_cast<__half2*>(prow + jn * 8 + cb) =
                        __floats2half2_rn(acc[im][jn][h * 2 + 0], acc[im][jn][h * 2 + 1]);
                }
            }
        }
    }
}

// ---------------- combine + aux: y[b] = sum_j sc_j * (sum_s P[s][loc_j] + b2[e_j]) ----------------
__global__ void __launch_bounds__(256)
combine_kernel(const float* __restrict__ b2, float* __restrict__ y) {
    const int b   = blockIdx.x;
    const int tid = threadIdx.x;                  // 256 threads x 4 cols -> 1024 cols
    const int l1 = g_loc[b * 2 + 0];
    const int l2 = g_loc[b * 2 + 1];
    const int e1 = l1 >> 12, e2 = l2 >> 12;       // NB = 4096 = 2^12
    const float s1 = g_scale[l1], s2 = g_scale[l2];

    float a0 = 0.f, a1 = 0.f, a2 = 0.f, a3 = 0.f;
    float c0 = 0.f, c1 = 0.f, c2 = 0.f, c3 = 0.f;
    #pragma unroll
    for (int s = 0; s < NSPL; s++) {
        const __half* r1 = g_part + ((size_t)s * (NE * NB) + l1) * NH + tid * 4;
        const __half* r2 = g_part + ((size_t)s * (NE * NB) + l2) * NH + tid * 4;
        uint2 u1 = *reinterpret_cast<const uint2*>(r1);
        uint2 u2 = *reinterpret_cast<const uint2*>(r2);
        float2 v;
        v = __half22float2(*reinterpret_cast<__half2*>(&u1.x)); a0 += v.x; a1 += v.y;
        v = __half22float2(*reinterpret_cast<__half2*>(&u1.y)); a2 += v.x; a3 += v.y;
        v = __half22float2(*reinterpret_cast<__half2*>(&u2.x)); c0 += v.x; c1 += v.y;
        v = __half22float2(*reinterpret_cast<__half2*>(&u2.y)); c2 += v.x; c3 += v.y;
    }
    const float4 bb1 = reinterpret_cast<const float4*>(b2 + (size_t)e1 * NH)[tid];
    const float4 bb2 = reinterpret_cast<const float4*>(b2 + (size_t)e2 * NH)[tid];
    float4 o;
    o.x = s1 * (a0 + bb1.x) + s2 * (c0 + bb2.x);
    o.y = s1 * (a1 + bb1.y) + s2 * (c1 + bb2.y);
    o.z = s1 * (a2 + bb1.z) + s2 * (c2 + bb2.z);
    o.w = s1 * (a3 + bb1.w) + s2 * (c3 + bb2.w);
    reinterpret_cast<float4*>(y + (size_t)b * NH)[tid] = o;

    // ---- aux loss (block 0 only; g_psum/g_rsum finalized in gate kernel) ----
    if (b == 0 && tid == 0) {
        float s = 0.f;
        #pragma unroll
        for (int e = 0; e < NE; e++)
            s += (g_psum[e] / (float)NB) * (g_rsum[e] / (float)NB);
        y[(size_t)NB * NH] = s * (float)NE;
    }
}

// ---------------- launch ----------------
extern "C" void kernel_launch(void* const* d_in, const int* in_sizes, int n_in,
                              void* d_out, int out_size) {
    const float* x  = (const float*)d_in[0];
    const float* gw = (const float*)d_in[1];
    const float* gb = (const float*)d_in[2];
    const float* w1 = (const float*)d_in[3];
    const float* b1 = (const float*)d_in[4];
    const float* w2 = (const float*)d_in[5];
    const float* b2 = (const float*)d_in[6];
    float* y = (float*)d_out;

    const int SMEM_BYTES = 3 * 10240 + 3 * 8704;   // 56832
    cudaFuncSetAttribute(moe_gemm<NH, ND, false, 1>,
                         cudaFuncAttributeMaxDynamicSharedMemorySize, SMEM_BYTES);
    cudaFuncSetAttribute(moe_gemm<ND / NSPL, NH, true, NSPL>,
                         cudaFuncAttributeMaxDynamicSharedMemorySize, SMEM_BYTES);

    prep_kernel<<<4736, 256>>>(w1, w2, x);                                  // #1 (all conversions)
    gate_kernel<<<NB, 256>>>(x, gw, gb);                                    // #2
    moe_gemm<NH, ND, false, 1>                                              // #3
        <<<dim3(ND / 128, NB / 128, NE), 256, SMEM_BYTES>>>(b1);
    moe_gemm<ND / NSPL, NH, true, NSPL>                                     // #4 (profiled)
        <<<dim3(NH / 128, NB / 128, NE * NSPL), 256, SMEM_BYTES>>>(b2);
    combine_kernel<<<NB, 256>>>(b2, y);                                     // #5 (+aux)
}

// round 13
// speedup vs baseline: 1.4854x; 1.0116x over previous
#include <cuda_runtime.h>
#include <cuda_fp16.h>
#include <cstdint>

#define NB 4096   // tokens
#define NH 1024   // hidden
#define ND 4096   // expert dim
#define NE 8      // experts
#define NSPL 4    // split-K for GEMM2 (fp16 partials via STG, no atomics)

// ---------------- scratch (__device__ globals: allocation-guard safe) ----------------
__device__ __half g_xh [(size_t)NB * NH];              //   8 MB
__device__ __half g_w1h[(size_t)NE * NH * ND];         //  64 MB
__device__ __half g_w2h[(size_t)NE * ND * NH];         //  64 MB
__device__ __half g_h  [(size_t)NE * NB * ND];         // 256 MB
__device__ __half g_part[(size_t)NSPL * NE * NB * NH]; // 256 MB fp16 split partials
__device__ int    g_cnt[NE];
__device__ int    g_idx[NE * NB];
__device__ float  g_scale[NE * NB];
__device__ int    g_loc[NB * 2];
__device__ float  g_psum[NE];
__device__ float  g_rsum[NE];

// ---------------- helpers ----------------
__device__ __forceinline__ uint32_t smem_u32(const void* p) {
    return (uint32_t)__cvta_generic_to_shared(p);
}
__device__ __forceinline__ void cp16(uint32_t smem, const void* gmem) {
    asm volatile("cp.async.cg.shared.global [%0], [%1], 16;\n"
                 :: "r"(smem), "l"(gmem) : "memory");
}

// ---------------- prep: w1 & w2 fp32->fp16 interleaved, zero routing state (launch #1) ----------------
__global__ void __launch_bounds__(256)
prep_kernel(const float* __restrict__ w1, const float* __restrict__ w2) {
    const size_t stride = (size_t)gridDim.x * 256;
    const size_t tid0   = (size_t)blockIdx.x * 256 + threadIdx.x;
    const size_t NW = (size_t)NE * NH * ND / 4;        // 8M float4 groups each
    for (size_t i = tid0; i < NW; i += stride) {
        float4 a = reinterpret_cast<const float4*>(w1)[i];   // two independent
        float4 b = reinterpret_cast<const float4*>(w2)[i];   // load streams (MLP)
        __half2* d1 = reinterpret_cast<__half2*>(g_w1h) + i * 2;
        __half2* d2 = reinterpret_cast<__half2*>(g_w2h) + i * 2;
        d1[0] = __floats2half2_rn(a.x, a.y);
        d1[1] = __floats2half2_rn(a.z, a.w);
        d2[0] = __floats2half2_rn(b.x, b.y);
        d2[1] = __floats2half2_rn(b.z, b.w);
    }
    if (tid0 < NE) { g_cnt[tid0] = 0; g_psum[tid0] = 0.f; g_rsum[tid0] = 0.f; }
}

// ---------------- gating + x fp32->fp16 (launch #2) ----------------
__global__ void gate_kernel(const float* __restrict__ x,
                            const float* __restrict__ gw,
                            const float* __restrict__ gb) {
    __shared__ float sx[NH];
    __shared__ float slog[NE];
    const int b = blockIdx.x, tid = threadIdx.x;
    for (int i = tid; i < NH; i += 256) sx[i] = x[(size_t)b * NH + i];
    __syncthreads();
    const int w = tid >> 5, lane = tid & 31;
    float s = 0.f;
    for (int i = lane; i < NH; i += 32) s += sx[i] * gw[i * NE + w];
    #pragma unroll
    for (int o = 16; o; o >>= 1) s += __shfl_xor_sync(0xffffffffu, s, o);
    if (lane == 0) slog[w] = s + gb[w];
    // x fp16 conversion from the smem copy (4 halves per thread)
    {
        const int i4 = tid;                        // 0..255 -> 4 elements each
        float4 v = reinterpret_cast<const float4*>(sx)[i4];
        __half2 h01 = __floats2half2_rn(v.x, v.y);
        __half2 h23 = __floats2half2_rn(v.z, v.w);
        uint2 pk;
        pk.x = *reinterpret_cast<uint32_t*>(&h01);
        pk.y = *reinterpret_cast<uint32_t*>(&h23);
        reinterpret_cast<uint2*>(&g_xh[(size_t)b * NH])[i4] = pk;
    }
    __syncthreads();
    if (tid == 0) {
        float p[NE];
        float mx = slog[0];
        #pragma unroll
        for (int e = 1; e < NE; e++) mx = fmaxf(mx, slog[e]);
        float den = 0.f;
        #pragma unroll
        for (int e = 0; e < NE; e++) { p[e] = expf(slog[e] - mx); den += p[e]; }
        float inv = 1.f / den;
        #pragma unroll
        for (int e = 0; e < NE; e++) p[e] *= inv;
        int e1 = 0; float p1 = p[0];
        #pragma unroll
        for (int e = 1; e < NE; e++) if (p[e] > p1) { p1 = p[e]; e1 = e; }
        int e2 = (e1 == 0) ? 1 : 0; float p2 = p[e2];
        #pragma unroll
        for (int e = 0; e < NE; e++)
            if (e != e1 && p[e] > p2) { p2 = p[e]; e2 = e; }
        int pos = atomicAdd(&g_cnt[e1], 1);
        g_idx[e1 * NB + pos] = b; g_scale[e1 * NB + pos] = p1 * 0.5f;
        g_loc[b * 2 + 0] = e1 * NB + pos;
        pos = atomicAdd(&g_cnt[e2], 1);
        g_idx[e2 * NB + pos] = b; g_scale[e2 * NB + pos] = p2 * 0.5f;
        g_loc[b * 2 + 1] = e2 * NB + pos;
        #pragma unroll
        for (int e = 0; e < NE; e++) atomicAdd(&g_psum[e], p[e]);
        atomicAdd(&g_rsum[e1], 1.f);
        atomicAdd(&g_rsum[e2], 1.f);
    }
}

// ---------------- grouped GEMM (R8 mainloop, FROZEN): CTA 128x128, 256 thr, warp 32x64,
//                  K-chunk 32, 3-stage ring, 1 sync/chunk ----------------
// smem/stage: A 128 x 80B = 10240, B 32 x 272B = 8704; 3 stages = 56832
// ISB==false: h = relu(Xg @ W1 + b1)   (bias via smem)
// ISB==true : g_part[split][e-slot] = Xh @ W2 chunk   (fp16 STG; combine reduces)
template<int KLEN, int NDIM, bool ISB, int NSPLIT>
__global__ void __launch_bounds__(256, 2)
moe_gemm(const float* __restrict__ bias) {
    constexpr int KT   = KLEN / 32;
    constexpr int ASTG = 10240, BSTG = 8704;
    const int zi    = blockIdx.z;
    const int e     = (NSPLIT == 1) ? zi : (zi >> 2);
    const int split = (NSPLIT == 1) ? 0  : (zi & 3);
    const int cnt = g_cnt[e];
    const int m0  = blockIdx.y * 128;
    if (m0 >= cnt) return;
    const int n0    = blockIdx.x * 128;
    const int kbase = split * KLEN;
    const int tid   = threadIdx.x;

    extern __shared__ __align__(1024) char smem[];
    __shared__ float sbias[128];
    const uint32_t sA = smem_u32(smem);          // 3 * 10240
    const uint32_t sB = sA + 3 * ASTG;           // 3 * 8704

    if (!ISB && tid < 128) sbias[tid] = bias[e * NDIM + n0 + tid];

    // ---- gmem source pointers ----
    const int ar = tid >> 1;                      // A row (0..127), 2 threads/row
    const __half* Arow;
    if (ISB) {
        Arow = g_h + ((size_t)e * NB + m0 + ar) * ND + kbase;
    } else {
        const int s0  = m0 + ar;
        const int tok = g_idx[e * NB + (s0 < cnt ? s0 : 0)];
        Arow = g_xh + (size_t)tok * NH;
    }
    const __half* W = (ISB ? g_w2h : g_w1h)
                    + (size_t)e * (size_t)(KLEN * NSPLIT) * NDIM
                    + (size_t)kbase * NDIM + n0;
    const int br = tid >> 3;                      // B row (0..31), 8 threads/row

    auto load_stage = [&](int chunk, int s) {
        const uint32_t as = sA + s * ASTG + ar * 80;
        const __half* ag = Arow + chunk * 32;
        #pragma unroll
        for (int j = 0; j < 2; j++) {
            const int c4 = (tid & 1) * 2 + j;     // 16B col 0..3
            cp16(as + c4 * 16, ag + c4 * 8);
        }
        const uint32_t bs = sB + s * BSTG + br * 272;
        const __half* bg = W + (size_t)(chunk * 32 + br) * NDIM;
        #pragma unroll
        for (int j = 0; j < 2; j++) {
            const int cc = (tid & 7) * 2 + j;     // 16B col 0..15
            cp16(bs + cc * 16, bg + cc * 8);
        }
        asm volatile("cp.async.commit_group;" ::: "memory");
    };

    float acc[2][8][4];
    #pragma unroll
    for (int i = 0; i < 2; i++)
        #pragma unroll
        for (int j = 0; j < 8; j++)
            #pragma unroll
            for (int q = 0; q < 4; q++) acc[i][j][q] = 0.f;

    const int lane = tid & 31, warp = tid >> 5;
    const int wm = (warp & 3) * 32, wn = (warp >> 2) * 64;
    const uint32_t aoff = (uint32_t)(wm + (lane & 15)) * 80 + (lane >> 4) * 16;
    const uint32_t boff = (uint32_t)(lane & 15) * 272 + (uint32_t)(wn + (lane >> 4) * 8) * 2;

    load_stage(0, 0);
    load_stage(1, 1);

    for (int i = 0; i < KT; i++) {
        if (i < KT - 1) asm volatile("cp.async.wait_group 1;" ::: "memory");
        else            asm volatile("cp.async.wait_group 0;" ::: "memory");
        __syncthreads();
        if (i + 2 < KT) {
            int sp = i + 2; sp -= (sp / 3) * 3;
            load_stage(i + 2, sp);
        }
        int s = i; s -= (s / 3) * 3;
        const uint32_t ab = sA + s * ASTG + aoff;
        const uint32_t bb = sB + s * BSTG + boff;
        #pragma unroll
        for (int ks = 0; ks < 2; ks++) {
            uint32_t a[2][4], b[4][4];
            #pragma unroll
            for (int im = 0; im < 2; im++) {
                asm volatile("ldmatrix.sync.aligned.m8n8.x4.shared.b16 {%0,%1,%2,%3}, [%4];"
                             : "=r"(a[im][0]), "=r"(a[im][1]), "=r"(a[im][2]), "=r"(a[im][3])
                             : "r"(ab + im * 16 * 80 + ks * 32));
            }
            #pragma unroll
            for (int g = 0; g < 4; g++) {
                asm volatile("ldmatrix.sync.aligned.m8n8.x4.trans.shared.b16 {%0,%1,%2,%3}, [%4];"
                             : "=r"(b[g][0]), "=r"(b[g][1]), "=r"(b[g][2]), "=r"(b[g][3])
                             : "r"(bb + ks * 16 * 272 + g * 32));
            }
            #pragma unroll
            for (int im = 0; im < 2; im++)
                #pragma unroll
                for (int jn = 0; jn < 8; jn++) {
                    const uint32_t b0 = b[jn >> 1][(jn & 1) * 2 + 0];
                    const uint32_t b1 = b[jn >> 1][(jn & 1) * 2 + 1];
                    asm volatile("mma.sync.aligned.m16n8k16.row.col.f32.f16.f16.f32 "
                                 "{%0,%1,%2,%3},{%4,%5,%6,%7},{%8,%9},{%0,%1,%2,%3};"
                                 : "+f"(acc[im][jn][0]), "+f"(acc[im][jn][1]),
                                   "+f"(acc[im][jn][2]), "+f"(acc[im][jn][3])
                                 : "r"(a[im][0]), "r"(a[im][1]), "r"(a[im][2]), "r"(a[im][3]),
                                   "r"(b0), "r"(b1));
                }
        }
    }

    // ---- epilogue ----
    const int rb = lane >> 2;
    const int cb = (lane & 3) * 2;
    #pragma unroll
    for (int im = 0; im < 2; im++) {
        #pragma unroll
        for (int h = 0; h < 2; h++) {
            const int row  = wm + im * 16 + rb + h * 8;
            const int slot = m0 + row;
            if (slot >= cnt) continue;
            if (!ISB) {
                __half* drow = &g_h[((size_t)e * NB + slot) * ND + n0 + wn];
                #pragma unroll
                for (int jn = 0; jn < 8; jn++) {
                    const int lc = wn + jn * 8 + cb;
                    float v0 = fmaxf(acc[im][jn][h * 2 + 0] + sbias[lc],     0.f);
                    float v1 = fmaxf(acc[im][jn][h * 2 + 1] + sbias[lc + 1], 0.f);
                    *reinterpret_cast<__half2*>(drow + jn * 8 + cb) = __floats2half2_rn(v0, v1);
                }
            } else {
                __half* prow = g_part + ((size_t)split * (NE * NB) + (size_t)e * NB + slot) * NH
                             + n0 + wn;
                #pragma unroll
                for (int jn = 0; jn < 8; jn++) {
                    *reinterpret_cast<__half2*>(prow + jn * 8 + cb) =
                        __floats2half2_rn(acc[im][jn][h * 2 + 0], acc[im][jn][h * 2 + 1]);
                }
            }
        }
    }
}

// ---------------- combine + aux: y[b] = sum_j sc_j * (sum_s P[s][loc_j] + b2[e_j]) ----------------
__global__ void __launch_bounds__(256)
combine_kernel(const float* __restrict__ b2, float* __restrict__ y) {
    const int b   = blockIdx.x;
    const int tid = threadIdx.x;                  // 256 threads x 4 cols -> 1024 cols
    const int l1 = g_loc[b * 2 + 0];
    const int l2 = g_loc[b * 2 + 1];
    const int e1 = l1 >> 12, e2 = l2 >> 12;       // NB = 4096 = 2^12
    const float s1 = g_scale[l1], s2 = g_scale[l2];

    float a0 = 0.f, a1 = 0.f, a2 = 0.f, a3 = 0.f;
    float c0 = 0.f, c1 = 0.f, c2 = 0.f, c3 = 0.f;
    #pragma unroll
    for (int s = 0; s < NSPL; s++) {
        const __half* r1 = g_part + ((size_t)s * (NE * NB) + l1) * NH + tid * 4;
        const __half* r2 = g_part + ((size_t)s * (NE * NB) + l2) * NH + tid * 4;
        uint2 u1 = *reinterpret_cast<const uint2*>(r1);
        uint2 u2 = *reinterpret_cast<const uint2*>(r2);
        float2 v;
        v = __half22float2(*reinterpret_cast<__half2*>(&u1.x)); a0 += v.x; a1 += v.y;
        v = __half22float2(*reinterpret_cast<__half2*>(&u1.y)); a2 += v.x; a3 += v.y;
        v = __half22float2(*reinterpret_cast<__half2*>(&u2.x)); c0 += v.x; c1 += v.y;
        v = __half22float2(*reinterpret_cast<__half2*>(&u2.y)); c2 += v.x; c3 += v.y;
    }
    const float4 bb1 = reinterpret_cast<const float4*>(b2 + (size_t)e1 * NH)[tid];
    const float4 bb2 = reinterpret_cast<const float4*>(b2 + (size_t)e2 * NH)[tid];
    float4 o;
    o.x = s1 * (a0 + bb1.x) + s2 * (c0 + bb2.x);
    o.y = s1 * (a1 + bb1.y) + s2 * (c1 + bb2.y);
    o.z = s1 * (a2 + bb1.z) + s2 * (c2 + bb2.z);
    o.w = s1 * (a3 + bb1.w) + s2 * (c3 + bb2.w);
    reinterpret_cast<float4*>(y + (size_t)b * NH)[tid] = o;

    // ---- aux loss (block 0 only; g_psum/g_rsum finalized in gate kernel) ----
    if (b == 0 && tid == 0) {
        float s = 0.f;
        #pragma unroll
        for (int e = 0; e < NE; e++)
            s += (g_psum[e] / (float)NB) * (g_rsum[e] / (float)NB);
        y[(size_t)NB * NH] = s * (float)NE;
    }
}

// ---------------- launch ----------------
extern "C" void kernel_launch(void* const* d_in, const int* in_sizes, int n_in,
                              void* d_out, int out_size) {
    const float* x  = (const float*)d_in[0];
    const float* gw = (const float*)d_in[1];
    const float* gb = (const float*)d_in[2];
    const float* w1 = (const float*)d_in[3];
    const float* b1 = (const float*)d_in[4];
    const float* w2 = (const float*)d_in[5];
    const float* b2 = (const float*)d_in[6];
    float* y = (float*)d_out;

    const int SMEM_BYTES = 3 * 10240 + 3 * 8704;   // 56832
    cudaFuncSetAttribute(moe_gemm<NH, ND, false, 1>,
                         cudaFuncAttributeMaxDynamicSharedMemorySize, SMEM_BYTES);
    cudaFuncSetAttribute(moe_gemm<ND / NSPL, NH, true, NSPL>,
                         cudaFuncAttributeMaxDynamicSharedMemorySize, SMEM_BYTES);

    prep_kernel<<<4736, 256>>>(w1, w2);                                     // #1 (w1+w2 interleaved)
    gate_kernel<<<NB, 256>>>(x, gw, gb);                                    // #2 (gate + x convert)
    moe_gemm<NH, ND, false, 1>                                              // #3
        <<<dim3(ND / 128, NB / 128, NE), 256, SMEM_BYTES>>>(b1);
    moe_gemm<ND / NSPL, NH, true, NSPL>                                     // #4 (profiled)
        <<<dim3(NH / 128, NB / 128, NE * NSPL), 256, SMEM_BYTES>>>(b2);
    combine_kernel<<<NB, 256>>>(b2, y);                                     // #5 (+aux)
}

// round 14
// speedup vs baseline: 1.5269x; 1.0279x over previous
#include <cuda_runtime.h>
#include <cuda_fp16.h>
#include <cstdint>

#define NB 4096   // tokens
#define NH 1024   // hidden
#define ND 4096   // expert dim
#define NE 8      // experts
#define NSPL 4    // split-K for GEMM2 (fp16 partials via STG, no atomics)
#define CONVB 4736  // conversion blocks in fused kernel

// ---------------- scratch (__device__ globals: allocation-guard safe) ----------------
// NOTE: zero-initialized at module load; combine_kernel re-zeroes counters at the
// end of every run, so every execution (eager or graph replay) sees zeroed state.
__device__ __half g_xh [(size_t)NB * NH];              //   8 MB
__device__ __half g_w1h[(size_t)NE * NH * ND];         //  64 MB
__device__ __half g_w2h[(size_t)NE * ND * NH];         //  64 MB
__device__ __half g_h  [(size_t)NE * NB * ND];         // 256 MB
__device__ __half g_part[(size_t)NSPL * NE * NB * NH]; // 256 MB fp16 split partials
__device__ int    g_cnt[NE];
__device__ int    g_idx[NE * NB];
__device__ float  g_scale[NE * NB];
__device__ int    g_loc[NB * 2];
__device__ float  g_psum[NE];
__device__ float  g_rsum[NE];

// ---------------- helpers ----------------
__device__ __forceinline__ uint32_t smem_u32(const void* p) {
    return (uint32_t)__cvta_generic_to_shared(p);
}
__device__ __forceinline__ void cp16(uint32_t smem, const void* gmem) {
    asm volatile("cp.async.cg.shared.global [%0], [%1], 16;\n"
                 :: "r"(smem), "l"(gmem) : "memory");
}

// ---------------- fused prep + gate (launch #1) ----------------
// blocks [0, NB)          : gating for token b = blockIdx.x, plus x fp32->fp16
// blocks [NB, NB+CONVB)   : w1 & w2 fp32->fp16, interleaved, 2x unrolled
__global__ void __launch_bounds__(256)
prep_gate_kernel(const float* __restrict__ x,
                 const float* __restrict__ gw,
                 const float* __restrict__ gb,
                 const float* __restrict__ w1,
                 const float* __restrict__ w2) {
    const int tid = threadIdx.x;

    if (blockIdx.x >= NB) {
        // ---- weight conversion role ----
        const size_t t   = (size_t)(blockIdx.x - NB) * 256 + tid;
        const size_t nst = (size_t)CONVB * 256;
        const size_t NW2 = (size_t)NE * NH * ND / 8;   // pairs of float4 groups
        const float4* w1q = reinterpret_cast<const float4*>(w1);
        const float4* w2q = reinterpret_cast<const float4*>(w2);
        for (size_t i = t; i < NW2; i += nst) {
            const size_t j = i * 2;
            float4 a0 = w1q[j], a1 = w1q[j + 1];       // 4 independent loads
            float4 b0 = w2q[j], b1 = w2q[j + 1];       // in flight (MLP=4)
            __half2* d1 = reinterpret_cast<__half2*>(g_w1h) + j * 2;
            __half2* d2 = reinterpret_cast<__half2*>(g_w2h) + j * 2;
            d1[0] = __floats2half2_rn(a0.x, a0.y);
            d1[1] = __floats2half2_rn(a0.z, a0.w);
            d1[2] = __floats2half2_rn(a1.x, a1.y);
            d1[3] = __floats2half2_rn(a1.z, a1.w);
            d2[0] = __floats2half2_rn(b0.x, b0.y);
            d2[1] = __floats2half2_rn(b0.z, b0.w);
            d2[2] = __floats2half2_rn(b1.x, b1.y);
            d2[3] = __floats2half2_rn(b1.z, b1.w);
        }
        return;
    }

    // ---- gating role ----
    __shared__ float sx[NH];
    __shared__ float slog[NE];
    const int b = blockIdx.x;
    for (int i = tid; i < NH; i += 256) sx[i] = x[(size_t)b * NH + i];
    __syncthreads();
    const int w = tid >> 5, lane = tid & 31;
    float s = 0.f;
    for (int i = lane; i < NH; i += 32) s += sx[i] * gw[i * NE + w];
    #pragma unroll
    for (int o = 16; o; o >>= 1) s += __shfl_xor_sync(0xffffffffu, s, o);
    if (lane == 0) slog[w] = s + gb[w];
    // x fp16 conversion from the smem copy (4 halves per thread)
    {
        float4 v = reinterpret_cast<const float4*>(sx)[tid];
        __half2 h01 = __floats2half2_rn(v.x, v.y);
        __half2 h23 = __floats2half2_rn(v.z, v.w);
        uint2 pk;
        pk.x = *reinterpret_cast<uint32_t*>(&h01);
        pk.y = *reinterpret_cast<uint32_t*>(&h23);
        reinterpret_cast<uint2*>(&g_xh[(size_t)b * NH])[tid] = pk;
    }
    __syncthreads();
    if (tid == 0) {
        float p[NE];
        float mx = slog[0];
        #pragma unroll
        for (int e = 1; e < NE; e++) mx = fmaxf(mx, slog[e]);
        float den = 0.f;
        #pragma unroll
        for (int e = 0; e < NE; e++) { p[e] = expf(slog[e] - mx); den += p[e]; }
        float inv = 1.f / den;
        #pragma unroll
        for (int e = 0; e < NE; e++) p[e] *= inv;
        int e1 = 0; float p1 = p[0];
        #pragma unroll
        for (int e = 1; e < NE; e++) if (p[e] > p1) { p1 = p[e]; e1 = e; }
        int e2 = (e1 == 0) ? 1 : 0; float p2 = p[e2];
        #pragma unroll
        for (int e = 0; e < NE; e++)
            if (e != e1 && p[e] > p2) { p2 = p[e]; e2 = e; }
        int pos = atomicAdd(&g_cnt[e1], 1);
        g_idx[e1 * NB + pos] = b; g_scale[e1 * NB + pos] = p1 * 0.5f;
        g_loc[b * 2 + 0] = e1 * NB + pos;
        pos = atomicAdd(&g_cnt[e2], 1);
        g_idx[e2 * NB + pos] = b; g_scale[e2 * NB + pos] = p2 * 0.5f;
        g_loc[b * 2 + 1] = e2 * NB + pos;
        #pragma unroll
        for (int e = 0; e < NE; e++) atomicAdd(&g_psum[e], p[e]);
        atomicAdd(&g_rsum[e1], 1.f);
        atomicAdd(&g_rsum[e2], 1.f);
    }
}

// ---------------- grouped GEMM (R8 mainloop, FROZEN): CTA 128x128, 256 thr, warp 32x64,
//                  K-chunk 32, 3-stage ring, 1 sync/chunk ----------------
// smem/stage: A 128 x 80B = 10240, B 32 x 272B = 8704; 3 stages = 56832
// ISB==false: h = relu(Xg @ W1 + b1)   (bias via smem)
// ISB==true : g_part[split][e-slot] = Xh @ W2 chunk   (fp16 STG; combine reduces)
template<int KLEN, int NDIM, bool ISB, int NSPLIT>
__global__ void __launch_bounds__(256, 2)
moe_gemm(const float* __restrict__ bias) {
    constexpr int KT   = KLEN / 32;
    constexpr int ASTG = 10240, BSTG = 8704;
    const int zi    = blockIdx.z;
    const int e     = (NSPLIT == 1) ? zi : (zi >> 2);
    const int split = (NSPLIT == 1) ? 0  : (zi & 3);
    const int cnt = g_cnt[e];
    const int m0  = blockIdx.y * 128;
    if (m0 >= cnt) return;
    const int n0    = blockIdx.x * 128;
    const int kbase = split * KLEN;
    const int tid   = threadIdx.x;

    extern __shared__ __align__(1024) char smem[];
    __shared__ float sbias[128];
    const uint32_t sA = smem_u32(smem);          // 3 * 10240
    const uint32_t sB = sA + 3 * ASTG;           // 3 * 8704

    if (!ISB && tid < 128) sbias[tid] = bias[e * NDIM + n0 + tid];

    // ---- gmem source pointers ----
    const int ar = tid >> 1;                      // A row (0..127), 2 threads/row
    const __half* Arow;
    if (ISB) {
        Arow = g_h + ((size_t)e * NB + m0 + ar) * ND + kbase;
    } else {
        const int s0  = m0 + ar;
        const int tok = g_idx[e * NB + (s0 < cnt ? s0 : 0)];
        Arow = g_xh + (size_t)tok * NH;
    }
    const __half* W = (ISB ? g_w2h : g_w1h)
                    + (size_t)e * (size_t)(KLEN * NSPLIT) * NDIM
                    + (size_t)kbase * NDIM + n0;
    const int br = tid >> 3;                      // B row (0..31), 8 threads/row

    auto load_stage = [&](int chunk, int s) {
        const uint32_t as = sA + s * ASTG + ar * 80;
        const __half* ag = Arow + chunk * 32;
        #pragma unroll
        for (int j = 0; j < 2; j++) {
            const int c4 = (tid & 1) * 2 + j;     // 16B col 0..3
            cp16(as + c4 * 16, ag + c4 * 8);
        }
        const uint32_t bs = sB + s * BSTG + br * 272;
        const __half* bg = W + (size_t)(chunk * 32 + br) * NDIM;
        #pragma unroll
        for (int j = 0; j < 2; j++) {
            const int cc = (tid & 7) * 2 + j;     // 16B col 0..15
            cp16(bs + cc * 16, bg + cc * 8);
        }
        asm volatile("cp.async.commit_group;" ::: "memory");
    };

    float acc[2][8][4];
    #pragma unroll
    for (int i = 0; i < 2; i++)
        #pragma unroll
        for (int j = 0; j < 8; j++)
            #pragma unroll
            for (int q = 0; q < 4; q++) acc[i][j][q] = 0.f;

    const int lane = tid & 31, warp = tid >> 5;
    const int wm = (warp & 3) * 32, wn = (warp >> 2) * 64;
    const uint32_t aoff = (uint32_t)(wm + (lane & 15)) * 80 + (lane >> 4) * 16;
    const uint32_t boff = (uint32_t)(lane & 15) * 272 + (uint32_t)(wn + (lane >> 4) * 8) * 2;

    load_stage(0, 0);
    load_stage(1, 1);

    for (int i = 0; i < KT; i++) {
        if (i < KT - 1) asm volatile("cp.async.wait_group 1;" ::: "memory");
        else            asm volatile("cp.async.wait_group 0;" ::: "memory");
        __syncthreads();
        if (i + 2 < KT) {
            int sp = i + 2; sp -= (sp / 3) * 3;
            load_stage(i + 2, sp);
        }
        int s = i; s -= (s / 3) * 3;
        const uint32_t ab = sA + s * ASTG + aoff;
        const uint32_t bb = sB + s * BSTG + boff;
        #pragma unroll
        for (int ks = 0; ks < 2; ks++) {
            uint32_t a[2][4], b[4][4];
            #pragma unroll
            for (int im = 0; im < 2; im++) {
                asm volatile("ldmatrix.sync.aligned.m8n8.x4.shared.b16 {%0,%1,%2,%3}, [%4];"
                             : "=r"(a[im][0]), "=r"(a[im][1]), "=r"(a[im][2]), "=r"(a[im][3])
                             : "r"(ab + im * 16 * 80 + ks * 32));
            }
            #pragma unroll
            for (int g = 0; g < 4; g++) {
                asm volatile("ldmatrix.sync.aligned.m8n8.x4.trans.shared.b16 {%0,%1,%2,%3}, [%4];"
                             : "=r"(b[g][0]), "=r"(b[g][1]), "=r"(b[g][2]), "=r"(b[g][3])
                             : "r"(bb + ks * 16 * 272 + g * 32));
            }
            #pragma unroll
            for (int im = 0; im < 2; im++)
                #pragma unroll
                for (int jn = 0; jn < 8; jn++) {
                    const uint32_t b0 = b[jn >> 1][(jn & 1) * 2 + 0];
                    const uint32_t b1 = b[jn >> 1][(jn & 1) * 2 + 1];
                    asm volatile("mma.sync.aligned.m16n8k16.row.col.f32.f16.f16.f32 "
                                 "{%0,%1,%2,%3},{%4,%5,%6,%7},{%8,%9},{%0,%1,%2,%3};"
                                 : "+f"(acc[im][jn][0]), "+f"(acc[im][jn][1]),
                                   "+f"(acc[im][jn][2]), "+f"(acc[im][jn][3])
                                 : "r"(a[im][0]), "r"(a[im][1]), "r"(a[im][2]), "r"(a[im][3]),
                                   "r"(b0), "r"(b1));
                }
        }
    }

    // ---- epilogue ----
    const int rb = lane >> 2;
    const int cb = (lane & 3) * 2;
    #pragma unroll
    for (int im = 0; im < 2; im++) {
        #pragma unroll
        for (int h = 0; h < 2; h++) {
            const int row  = wm + im * 16 + rb + h * 8;
            const int slot = m0 + row;
            if (slot >= cnt) continue;
            if (!ISB) {
                __half* drow = &g_h[((size_t)e * NB + slot) * ND + n0 + wn];
                #pragma unroll
                for (int jn = 0; jn < 8; jn++) {
                    const int lc = wn + jn * 8 + cb;
                    float v0 = fmaxf(acc[im][jn][h * 2 + 0] + sbias[lc],     0.f);
                    float v1 = fmaxf(acc[im][jn][h * 2 + 1] + sbias[lc + 1], 0.f);
                    *reinterpret_cast<__half2*>(drow + jn * 8 + cb) = __floats2half2_rn(v0, v1);
                }
            } else {
                __half* prow = g_part + ((size_t)split * (NE * NB) + (size_t)e * NB + slot) * NH
                             + n0 + wn;
                #pragma unroll
                for (int jn = 0; jn < 8; jn++) {
                    *reinterpret_cast<__half2*>(prow + jn * 8 + cb) =
                        __floats2half2_rn(acc[im][jn][h * 2 + 0], acc[im][jn][h * 2 + 1]);
                }
            }
        }
    }
}

// ---------------- combine + aux + counter re-zero (launch #4) ----------------
__global__ void __launch_bounds__(256)
combine_kernel(const float* __restrict__ b2, float* __restrict__ y) {
    const int b   = blockIdx.x;
    const int tid = threadIdx.x;                  // 256 threads x 4 cols -> 1024 cols
    const int l1 = g_loc[b * 2 + 0];
    const int l2 = g_loc[b * 2 + 1];
    const int e1 = l1 >> 12, e2 = l2 >> 12;       // NB = 4096 = 2^12
    const float s1 = g_scale[l1], s2 = g_scale[l2];

    float a0 = 0.f, a1 = 0.f, a2 = 0.f, a3 = 0.f;
    float c0 = 0.f, c1 = 0.f, c2 = 0.f, c3 = 0.f;
    #pragma unroll
    for (int s = 0; s < NSPL; s++) {
        const __half* r1 = g_part + ((size_t)s * (NE * NB) + l1) * NH + tid * 4;
        const __half* r2 = g_part + ((size_t)s * (NE * NB) + l2) * NH + tid * 4;
        uint2 u1 = *reinterpret_cast<const uint2*>(r1);
        uint2 u2 = *reinterpret_cast<const uint2*>(r2);
        float2 v;
        v = __half22float2(*reinterpret_cast<__half2*>(&u1.x)); a0 += v.x; a1 += v.y;
        v = __half22float2(*reinterpret_cast<__half2*>(&u1.y)); a2 += v.x; a3 += v.y;
        v = __half22float2(*reinterpret_cast<__half2*>(&u2.x)); c0 += v.x; c1 += v.y;
        v = __half22float2(*reinterpret_cast<__half2*>(&u2.y)); c2 += v.x; c3 += v.y;
    }
    const float4 bb1 = reinterpret_cast<const float4*>(b2 + (size_t)e1 * NH)[tid];
    const float4 bb2 = reinterpret_cast<const float4*>(b2 + (size_t)e2 * NH)[tid];
    float4 o;
    o.x = s1 * (a0 + bb1.x) + s2 * (c0 + bb2.x);
    o.y = s1 * (a1 + bb1.y) + s2 * (c1 + bb2.y);
    o.z = s1 * (a2 + bb1.z) + s2 * (c2 + bb2.z);
    o.w = s1 * (a3 + bb1.w) + s2 * (c3 + bb2.w);
    reinterpret_cast<float4*>(y + (size_t)b * NH)[tid] = o;

    // ---- aux loss + counter re-zero for the NEXT run (block 0 only) ----
    if (b == 0 && tid == 0) {
        float s = 0.f;
        #pragma unroll
        for (int e = 0; e < NE; e++)
            s += (g_psum[e] / (float)NB) * (g_rsum[e] / (float)NB);
        y[(size_t)NB * NH] = s * (float)NE;
        #pragma unroll
        for (int e = 0; e < NE; e++) { g_cnt[e] = 0; g_psum[e] = 0.f; g_rsum[e] = 0.f; }
    }
}

// ---------------- launch ----------------
extern "C" void kernel_launch(void* const* d_in, const int* in_sizes, int n_in,
                              void* d_out, int out_size) {
    const float* x  = (const float*)d_in[0];
    const float* gw = (const float*)d_in[1];
    const float* gb = (const float*)d_in[2];
    const float* w1 = (const float*)d_in[3];
    const float* b1 = (const float*)d_in[4];
    const float* w2 = (const float*)d_in[5];
    const float* b2 = (const float*)d_in[6];
    float* y = (float*)d_out;

    const int SMEM_BYTES = 3 * 10240 + 3 * 8704;   // 56832
    cudaFuncSetAttribute(moe_gemm<NH, ND, false, 1>,
                         cudaFuncAttributeMaxDynamicSharedMemorySize, SMEM_BYTES);
    cudaFuncSetAttribute(moe_gemm<ND / NSPL, NH, true, NSPL>,
                         cudaFuncAttributeMaxDynamicSharedMemorySize, SMEM_BYTES);

    prep_gate_kernel<<<NB + CONVB, 256>>>(x, gw, gb, w1, w2);               // #1 (gate + conversions)
    moe_gemm<NH, ND, false, 1>                                              // #2
        <<<dim3(ND / 128, NB / 128, NE), 256, SMEM_BYTES>>>(b1);
    moe_gemm<ND / NSPL, NH, true, NSPL>                                     // #3
        <<<dim3(NH / 128, NB / 128, NE * NSPL), 256, SMEM_BYTES>>>(b2);
    combine_kernel<<<NB, 256>>>(b2, y);                                     // #4 (+aux, +re-zero)
}